// round 13
// baseline (speedup 1.0000x reference)
#include <cuda_runtime.h>
#include <cuda_bf16.h>
#include <math.h>

#define B 64
#define H 512
#define EMB 512
#define V 32000
#define S_ENC 512
#define S_SEQ 512
#define ENC2 512
#define OOV 50
#define VE (V + OOV) /* 32050 */
#define NEGINF (-1e12f)
#define BVE ((size_t)B * VE)

// ---------------- scratch (device globals) -----------------------------------
__device__ float    g_cat[B * 1024];
__device__ float    g_x[B * EMB];
__device__ float    g_gates[B * 4 * H];
__device__ float    g_h1[B * H];
__device__ float    g_keyp[B * H];
__device__ float    g_kb[B];
__device__ float    g_energies[B * S_ENC];
__device__ float    g_cat2[B * 1024];
__device__ float    g_comb[B * H];
__device__ float    g_seqE[B * S_SEQ];
__device__ __nv_bfloat16 g_seqs_bf[(size_t)B * S_SEQ * ENC2]; // 33.5MB
__device__ __nv_bfloat16 g_wsk_bf[H * ENC2];                  // 0.5MB

__device__ __forceinline__ float sigmoidf_(float x) { return 1.f / (1.f + expf(-x)); }
__device__ __forceinline__ unsigned ordf(float f) {
    unsigned u = __float_as_uint(f);
    return (u & 0x80000000u) ? ~u : (u | 0x80000000u);
}
__device__ __forceinline__ float iordf(unsigned u) {
    return (u & 0x80000000u) ? __uint_as_float(u ^ 0x80000000u) : __uint_as_float(~u);
}
__device__ __forceinline__ unsigned pack_bf2(float x, float y) {
    __nv_bfloat162 h = __floats2bfloat162_rn(x, y);
    return *reinterpret_cast<unsigned*>(&h);
}
__device__ __forceinline__ unsigned swz(unsigned byte_off) {
    return byte_off ^ ((byte_off >> 3) & 0x70); // 128B-row swizzle
}
// swizzle for 1024B rows: XOR 16B-unit index with (row&7)
__device__ __forceinline__ unsigned swzA(int row, int byteInRow) {
    return (unsigned)(row * 1024 + ((((byteInRow >> 4) ^ (row & 7)) << 4) | (byteInRow & 15)));
}

#define MMA16816(C, A, B0, B1) asm volatile( \
    "mma.sync.aligned.m16n8k16.row.col.f32.bf16.bf16.f32 " \
    "{%0,%1,%2,%3},{%4,%5,%6,%7},{%8,%9},{%0,%1,%2,%3};" \
    : "+f"(C[0]), "+f"(C[1]), "+f"(C[2]), "+f"(C[3]) \
    : "r"(A[0]), "r"(A[1]), "r"(A[2]), "r"(A[3]), "r"(B0), "r"(B1))

#define LDMX4(R, ADDR) asm volatile( \
    "ldmatrix.sync.aligned.m8n8.x4.shared.b16 {%0,%1,%2,%3},[%4];" \
    : "=r"(R[0]), "=r"(R[1]), "=r"(R[2]), "=r"(R[3]) : "r"(ADDR))

// ---------------- init --------------------------------------------------------
__global__ void init_kernel(const int* __restrict__ ids,
                            const float* __restrict__ prev_ctx,
                            const float* __restrict__ embed,
                            const float* __restrict__ seqs,
                            const float* __restrict__ W_seqkey,
                            float* __restrict__ out) {
    int stride = gridDim.x * blockDim.x;
    int i0 = blockIdx.x * blockDim.x + threadIdx.x;
    for (int j = i0; j < B; j += stride) g_kb[j] = 0.f;
    for (int j = i0; j < B * OOV; j += stride) {
        int b = j / OOV, k = j % OOV;
        out[b * VE + V + k] = 0.f;
    }
    for (int j = i0; j < B * S_SEQ; j += stride) g_seqE[j] = 0.f;
    for (int j = i0; j < B * EMB; j += stride) g_x[j] = 0.f;
    for (int j = i0; j < B * 4 * H; j += stride) g_gates[j] = 0.f;
    for (int j = i0; j < B * H; j += stride) {
        g_comb[j] = 0.f;
        out[BVE + j] = 0.f; // ctx region of out (context_kernel atomicAdds here)
    }
    for (int j = i0; j < B * 1024; j += stride) {
        int b = j >> 10, k = j & 1023;
        g_cat[j] = (k < EMB) ? embed[(size_t)ids[b] * EMB + k] : prev_ctx[b * H + (k - EMB)];
        if (k >= 512) g_cat2[j] = 0.f;
    }
    // bf16 conversions (vectorized by 4)
    {
        const size_t n4 = (size_t)B * S_SEQ * ENC2 / 4;
        const float4* src = (const float4*)seqs;
        uint2* dst = (uint2*)g_seqs_bf;
        for (size_t j = i0; j < n4; j += stride) {
            float4 f = src[j];
            dst[j] = make_uint2(pack_bf2(f.x, f.y), pack_bf2(f.z, f.w));
        }
    }
    {
        const size_t n4 = (size_t)H * ENC2 / 4;
        const float4* src = (const float4*)W_seqkey;
        uint2* dst = (uint2*)g_wsk_bf;
        for (size_t j = i0; j < n4; j += stride) {
            float4 f = src[j];
            dst[j] = make_uint2(pack_bf2(f.x, f.y), pack_bf2(f.z, f.w));
        }
    }
}

// ---------------- split-K SIMT GEMM (M=64): atomicAdd epilogue ----------------
#define BM 64
#define BN 64
#define BK 16
__device__ __forceinline__ void gemm_body(const float* __restrict__ A, int lda,
                                          const float* __restrict__ Bw, int ldb,
                                          float* __restrict__ C, int ldc,
                                          int K, int nsplit,
                                          const float* __restrict__ bias) {
    __shared__ float As[BK][BM + 1];
    __shared__ float Bs[BK][BN + 1];
    int tid = threadIdx.x;
    int n0 = blockIdx.x * BN;
    int kslice = K / nsplit;
    int kbeg = blockIdx.z * kslice;
    int tm = (tid / 16) * 4;
    int tn = (tid % 16) * 4;
    float acc[4][4] = {};
    int lrow = tid >> 2;
    int lkc = (tid & 3) * 4;

    for (int k0 = kbeg; k0 < kbeg + kslice; k0 += BK) {
        float4 av = *reinterpret_cast<const float4*>(A + (size_t)lrow * lda + k0 + lkc);
        As[lkc + 0][lrow] = av.x; As[lkc + 1][lrow] = av.y;
        As[lkc + 2][lrow] = av.z; As[lkc + 3][lrow] = av.w;
        float4 bv = *reinterpret_cast<const float4*>(Bw + (size_t)(n0 + lrow) * ldb + k0 + lkc);
        Bs[lkc + 0][lrow] = bv.x; Bs[lkc + 1][lrow] = bv.y;
        Bs[lkc + 2][lrow] = bv.z; Bs[lkc + 3][lrow] = bv.w;
        __syncthreads();
#pragma unroll
        for (int kk = 0; kk < BK; ++kk) {
            float a0 = As[kk][tm + 0], a1 = As[kk][tm + 1];
            float a2 = As[kk][tm + 2], a3 = As[kk][tm + 3];
            float b0 = Bs[kk][tn + 0], b1 = Bs[kk][tn + 1];
            float b2 = Bs[kk][tn + 2], b3 = Bs[kk][tn + 3];
            acc[0][0] += a0 * b0; acc[0][1] += a0 * b1; acc[0][2] += a0 * b2; acc[0][3] += a0 * b3;
            acc[1][0] += a1 * b0; acc[1][1] += a1 * b1; acc[1][2] += a1 * b2; acc[1][3] += a1 * b3;
            acc[2][0] += a2 * b0; acc[2][1] += a2 * b1; acc[2][2] += a2 * b2; acc[2][3] += a2 * b3;
            acc[3][0] += a3 * b0; acc[3][1] += a3 * b1; acc[3][2] += a3 * b2; acc[3][3] += a3 * b3;
        }
        __syncthreads();
    }
#pragma unroll
    for (int i = 0; i < 4; i++)
#pragma unroll
        for (int j = 0; j < 4; j++) {
            int cgl = n0 + tn + j;
            float v = acc[i][j];
            if (bias && blockIdx.z == 0) v += bias[cgl];
            atomicAdd(C + (size_t)(tm + i) * ldc + cgl, v);
        }
}

__global__ void gemm_sk(const float* __restrict__ A, int lda,
                        const float* __restrict__ Bw, int ldb,
                        float* __restrict__ C, int ldc,
                        int K, const float* __restrict__ bias) {
    gemm_body(A, lda, Bw, ldb, C, ldc, K, gridDim.z, bias);
}

__global__ void gemm_dual(const float* __restrict__ Wr,
                          const float* __restrict__ br,
                          const float* __restrict__ h0,
                          const float* __restrict__ Whh) {
    if (blockIdx.y == 0) {
        if (blockIdx.x >= EMB / BN) return;
        gemm_body(g_cat, 1024, Wr, 1024, g_x, EMB, 1024, gridDim.z, br);
    } else {
        gemm_body(h0, H, Whh, H, g_gates, 4 * H, H, gridDim.z, nullptr);
    }
}

// ---------------- LSTM elementwise + kb reduction (shuffle + atomic) -----------
__global__ void __launch_bounds__(512) lstm_kernel(
    const float* __restrict__ c0, const float* __restrict__ b_ih,
    const float* __restrict__ b_hh, const float* __restrict__ b_key,
    float* __restrict__ out) {
    int b = blockIdx.x, h = threadIdx.x;
    const float* gr = g_gates + b * 4 * H;
    float ig = sigmoidf_(gr[h] + b_ih[h] + b_hh[h]);
    float fg = sigmoidf_(gr[H + h] + b_ih[H + h] + b_hh[H + h]);
    float gg = tanhf(gr[2 * H + h] + b_ih[2 * H + h] + b_hh[2 * H + h]);
    float og = sigmoidf_(gr[3 * H + h] + b_ih[3 * H + h] + b_hh[3 * H + h]);
    float c1 = fg * c0[b * H + h] + ig * gg;
    float h1 = og * tanhf(c1);
    g_h1[b * H + h] = h1;
    g_cat2[b * 1024 + h] = h1;
    out[BVE + B * H + b * H + h] = h1;
    out[BVE + 2 * B * H + b * H + h] = c1;
    float val = b_key[h] * h1;
    for (int o = 16; o; o >>= 1) val += __shfl_down_sync(0xffffffffu, val, o);
    if ((h & 31) == 0) atomicAdd(&g_kb[b], val);
}

// ---------------- key projection ------------------------------------------------
__global__ void __launch_bounds__(256) keyproj_kernel(const float* __restrict__ W_key) {
    int b = blockIdx.x, nc = blockIdx.y;
    int t = threadIdx.x;
    __shared__ float hs[H];
    __shared__ float part[4][64];
    hs[t] = g_h1[b * H + t];
    hs[t + 256] = g_h1[b * H + t + 256];
    __syncthreads();
    int n = nc * 64 + (t & 63);
    int hp = t >> 6;
    const float* wp = W_key + (size_t)(hp * 128) * H + n;
    const float* hh = hs + hp * 128;
    float acc = 0.f;
#pragma unroll 16
    for (int k = 0; k < 128; k++) acc += hh[k] * wp[(size_t)k * H];
    part[hp][t & 63] = acc;
    __syncthreads();
    if (t < 64)
        g_keyp[b * H + nc * 64 + t] = part[0][t] + part[1][t] + part[2][t] + part[3][t];
}

// ---------------- fused energies + softmax (per batch) -------------------------
__global__ void __launch_bounds__(512) energysoftmax_kernel(const float* __restrict__ enc,
                                                            float* __restrict__ out) {
    int b = blockIdx.x, t = threadIdx.x;
    __shared__ float kp[H];
    __shared__ float w[S_ENC];
    __shared__ float red[S_ENC];
    kp[t] = g_keyp[b * H + t];
    __syncthreads();
    float kb = g_kb[b];
    int warp = t >> 5, lane = t & 31;
    for (int i = 0; i < S_ENC / 16; i++) {
        int s = i * 16 + warp;
        const float* er = enc + ((size_t)b * S_ENC + s) * H;
        float e = 0.f, sm = 0.f;
#pragma unroll 4
        for (int k = lane; k < H; k += 32) {
            float x = er[k];
            e += x * kp[k];
            sm += x;
        }
        for (int o = 16; o; o >>= 1) {
            e += __shfl_down_sync(0xffffffffu, e, o);
            sm += __shfl_down_sync(0xffffffffu, sm, o);
        }
        if (lane == 0) w[s] = (sm == 0.f) ? 1e-12f : (e + kb);
    }
    __syncthreads();
    float e = w[t];
    red[t] = e;
    __syncthreads();
    for (int s = 256; s; s >>= 1) { if (t < s) red[t] = fmaxf(red[t], red[t + s]); __syncthreads(); }
    float m = red[0];
    __syncthreads();
    float ex = expf(e - m);
    red[t] = ex;
    __syncthreads();
    for (int s = 256; s; s >>= 1) { if (t < s) red[t] += red[t + s]; __syncthreads(); }
    float wt = ex / red[0];
    g_energies[b * S_ENC + t] = wt;
    out[BVE + 3 * B * H + b * S_ENC + t] = wt;
}

// context: accumulates into g_cat2 AND directly into out ctx region (init zeroed)
__global__ void context_kernel(const float* __restrict__ enc, float* __restrict__ out) {
    int b = blockIdx.x, chunk = blockIdx.y, h = threadIdx.x;
    int s0 = chunk * 64;
    const float* w = g_energies + b * S_ENC;
    const float* er = enc + ((size_t)b * S_ENC + s0) * H + h;
    float acc = 0.f;
#pragma unroll 4
    for (int s = 0; s < 64; s++) acc += w[s0 + s] * er[(size_t)s * H];
    atomicAdd(&g_cat2[b * 1024 + 512 + h], acc);
    atomicAdd(&out[BVE + b * H + h], acc);
}

// ---------------- W_out MMA: A = tanh(g_comb) converted in-kernel --------------
__global__ void __launch_bounds__(128) wout_mma(const float* __restrict__ W_out,
                                                const float* __restrict__ b_out,
                                                float* __restrict__ out) {
    extern __shared__ char dynsm[];
    char* smA = dynsm;              // 65536
    char* smB = dynsm + 65536;      // 2 * 8192
    int tid = threadIdx.x;
    int warp = tid >> 5, lane = tid & 31;
    int wm = warp & 1, wn = warp >> 1;
    int n0 = blockIdx.x * 64;
    unsigned a_base = (unsigned)__cvta_generic_to_shared(smA);
    unsigned b_base = (unsigned)__cvta_generic_to_shared(smB);
    int lrow = lane & 15, lk = (lane >> 4) * 8;

    // load full A: tanh(g_comb) fp32 -> bf16 swizzled smem (64x512)
#pragma unroll
    for (int i = 0; i < 32; i++) {
        int ch = i * 128 + tid;
        int r = ch >> 6, c = ch & 63;
        const float* src = g_comb + r * H + c * 8;
        float4 f0 = *(const float4*)(src);
        float4 f1 = *(const float4*)(src + 4);
        uint4 v;
        v.x = pack_bf2(tanhf(f0.x), tanhf(f0.y));
        v.y = pack_bf2(tanhf(f0.z), tanhf(f0.w));
        v.z = pack_bf2(tanhf(f1.x), tanhf(f1.y));
        v.w = pack_bf2(tanhf(f1.z), tanhf(f1.w));
        *(uint4*)(smA + swzA(r, c * 16)) = v;
    }

    float acc[2][4][4] = {};
    float4 f[4][2];
#pragma unroll
    for (int i = 0; i < 4; i++) {
        int ch = i * 128 + tid, r = ch >> 3, c = ch & 7;
        const float* src = W_out + (size_t)(n0 + r) * H + c * 8;
        f[i][0] = *(const float4*)(src);
        f[i][1] = *(const float4*)(src + 4);
    }
    for (int kc = 0; kc < H / 64; kc++) {
        char* buf = smB + (kc & 1) * 8192;
#pragma unroll
        for (int i = 0; i < 4; i++) {
            int ch = i * 128 + tid, r = ch >> 3, c = ch & 7;
            uint4 v;
            v.x = pack_bf2(f[i][0].x, f[i][0].y);
            v.y = pack_bf2(f[i][0].z, f[i][0].w);
            v.z = pack_bf2(f[i][1].x, f[i][1].y);
            v.w = pack_bf2(f[i][1].z, f[i][1].w);
            *(uint4*)(buf + swz(r * 128 + c * 16)) = v;
        }
        __syncthreads();
        if (kc + 1 < H / 64) {
            int k0 = (kc + 1) * 64;
#pragma unroll
            for (int i = 0; i < 4; i++) {
                int ch = i * 128 + tid, r = ch >> 3, c = ch & 7;
                const float* src = W_out + (size_t)(n0 + r) * H + k0 + c * 8;
                f[i][0] = *(const float4*)(src);
                f[i][1] = *(const float4*)(src + 4);
            }
        }
        unsigned bbuf = b_base + (kc & 1) * 8192;
#pragma unroll
        for (int ks = 0; ks < 4; ks++) {
            unsigned af[2][4], bfm[2][4];
#pragma unroll
            for (int mf = 0; mf < 2; mf++) {
                int row = wm * 32 + mf * 16 + lrow;
                LDMX4(af[mf], a_base + swzA(row, (kc * 64 + ks * 16 + lk) * 2));
            }
#pragma unroll
            for (int nh = 0; nh < 2; nh++) {
                int row = wn * 32 + nh * 16 + lrow;
                LDMX4(bfm[nh], bbuf + swz(row * 128 + (ks * 16 + lk) * 2));
            }
#pragma unroll
            for (int mf = 0; mf < 2; mf++)
#pragma unroll
                for (int nf = 0; nf < 4; nf++) {
                    int nh = nf >> 1, nl = nf & 1;
                    MMA16816(acc[mf][nf], af[mf], bfm[nh][nl], bfm[nh][nl + 2]);
                }
        }
    }
    int qr = lane >> 2, qc = lane & 3;
#pragma unroll
    for (int mf = 0; mf < 2; mf++) {
        int m0 = wm * 32 + mf * 16 + qr;
#pragma unroll
        for (int nf = 0; nf < 4; nf++) {
            int n = n0 + wn * 32 + nf * 8 + qc * 2;
            float bo0 = b_out[n], bo1 = b_out[n + 1];
            out[(size_t)m0 * VE + n]           = acc[mf][nf][0] + bo0;
            out[(size_t)m0 * VE + n + 1]       = acc[mf][nf][1] + bo1;
            out[(size_t)(m0 + 8) * VE + n]     = acc[mf][nf][2] + bo0;
            out[(size_t)(m0 + 8) * VE + n + 1] = acc[mf][nf][3] + bo1;
        }
    }
}

// ---------------- tensor-core seqkey (R5/R9 structure, bf16 A) -----------------
__global__ void __launch_bounds__(128) seqkey_mma() {
    __shared__ __align__(128) __nv_bfloat16 As[64 * 64];
    __shared__ __align__(128) __nv_bfloat16 Bs[64 * 64];
    int tid = threadIdx.x;
    int warp = tid >> 5, lane = tid & 31;
    int wm = warp & 1, wn = warp >> 1;
    int n0 = blockIdx.x * 64, s0 = blockIdx.y * 64, b = blockIdx.z;
    const __nv_bfloat16* Ag = g_seqs_bf + ((size_t)b * S_SEQ + s0) * ENC2;
    const __nv_bfloat16* Bg = g_wsk_bf + (size_t)n0 * ENC2;

    float acc[2][4][4] = {};
    unsigned a_base = (unsigned)__cvta_generic_to_shared(As);
    unsigned b_base = (unsigned)__cvta_generic_to_shared(Bs);
    int lrow = lane & 15, lk = (lane >> 4) * 8;

    uint4 pa[4], pb[4];
#pragma unroll
    for (int i = 0; i < 4; i++) {
        int ch = i * 128 + tid, r = ch >> 3, c = ch & 7;
        pa[i] = *(const uint4*)(Ag + (size_t)r * ENC2 + c * 8);
        pb[i] = *(const uint4*)(Bg + (size_t)r * ENC2 + c * 8);
    }
    for (int kc = 0; kc < ENC2 / 64; kc++) {
#pragma unroll
        for (int i = 0; i < 4; i++) {
            int ch = i * 128 + tid, r = ch >> 3, c = ch & 7;
            unsigned off = swz(r * 128 + c * 16);
            *(uint4*)((char*)As + off) = pa[i];
            *(uint4*)((char*)Bs + off) = pb[i];
        }
        __syncthreads();
        if (kc + 1 < ENC2 / 64) {
            int k0 = (kc + 1) * 64;
#pragma unroll
            for (int i = 0; i < 4; i++) {
                int ch = i * 128 + tid, r = ch >> 3, c = ch & 7;
                pa[i] = *(const uint4*)(Ag + (size_t)r * ENC2 + k0 + c * 8);
                pb[i] = *(const uint4*)(Bg + (size_t)r * ENC2 + k0 + c * 8);
            }
        }
#pragma unroll
        for (int ks = 0; ks < 4; ks++) {
            int kb = ks * 16;
            unsigned af[2][4], bfm[2][4];
#pragma unroll
            for (int mf = 0; mf < 2; mf++) {
                int row = wm * 32 + mf * 16 + lrow;
                LDMX4(af[mf], a_base + swz(row * 128 + (kb + lk) * 2));
            }
#pragma unroll
            for (int nh = 0; nh < 2; nh++) {
                int row = wn * 32 + nh * 16 + lrow;
                LDMX4(bfm[nh], b_base + swz(row * 128 + (kb + lk) * 2));
            }
#pragma unroll
            for (int mf = 0; mf < 2; mf++)
#pragma unroll
                for (int nf = 0; nf < 4; nf++) {
                    int nh = nf >> 1, nl = nf & 1;
                    MMA16816(acc[mf][nf], af[mf], bfm[nh][nl], bfm[nh][nl + 2]);
                }
        }
        __syncthreads();
    }
    const float* h1p = g_h1 + b * H + n0 + wn * 32;
    int qr = lane >> 2, qc = lane & 3;
#pragma unroll
    for (int mf = 0; mf < 2; mf++) {
        float s0v = 0.f, s1v = 0.f;
#pragma unroll
        for (int nf = 0; nf < 4; nf++) {
            float h0v = h1p[nf * 8 + qc * 2 + 0];
            float h1v = h1p[nf * 8 + qc * 2 + 1];
            s0v += tanhf(acc[mf][nf][0]) * h0v + tanhf(acc[mf][nf][1]) * h1v;
            s1v += tanhf(acc[mf][nf][2]) * h0v + tanhf(acc[mf][nf][3]) * h1v;
        }
        s0v += __shfl_xor_sync(0xffffffffu, s0v, 1);
        s0v += __shfl_xor_sync(0xffffffffu, s0v, 2);
        s1v += __shfl_xor_sync(0xffffffffu, s1v, 1);
        s1v += __shfl_xor_sync(0xffffffffu, s1v, 2);
        if (qc == 0) {
            int srow = s0 + wm * 32 + mf * 16 + qr;
            atomicAdd(&g_seqE[b * S_SEQ + srow], s0v);
            atomicAdd(&g_seqE[b * S_SEQ + srow + 8], s1v);
        }
    }
}

// ---------------- final: smem scatter-max + register-cached log_softmax --------
#define FINAL_SMEM (VE * 4 + 1024 * 4)
__global__ void __launch_bounds__(1024) final_kernel(float* __restrict__ out,
                                                     const unsigned char* __restrict__ mask,
                                                     const int* __restrict__ ext) {
    extern __shared__ char dynsm[];
    unsigned* copy_s = (unsigned*)dynsm;
    float* sh = (float*)(dynsm + VE * 4);
    int b = blockIdx.x, t = threadIdx.x;
    unsigned negord = ordf(NEGINF);
    for (int j = t; j < VE; j += 1024) copy_s[j] = negord;
    __syncthreads();
    if (t < 512) {
        float e = mask[b * S_SEQ + t] ? 1e-12f : g_seqE[b * S_SEQ + t];
        atomicMax(&copy_s[ext[b * S_SEQ + t]], ordf(e));
    }
    __syncthreads();
    float* row = out + (size_t)b * VE;
    float v[32];
    float mx = -INFINITY;
#pragma unroll
    for (int i = 0; i < 32; i++) {
        int j = t + i * 1024;
        if (j < VE) {
            float lg = row[j];
            float cf = iordf(copy_s[j]);
            if (cf == NEGINF) cf = 0.f;
            float val = lg + cf;
            if (val == 0.f) val = NEGINF;
            v[i] = val;
            mx = fmaxf(mx, val);
        } else {
            v[i] = NEGINF;
        }
    }
    sh[t] = mx;
    __syncthreads();
    for (int s = 512; s; s >>= 1) { if (t < s) sh[t] = fmaxf(sh[t], sh[t + s]); __syncthreads(); }
    float m = sh[0];
    __syncthreads();
    float sum = 0.f;
#pragma unroll
    for (int i = 0; i < 32; i++) sum += expf(v[i] - m);
    sh[t] = sum;
    __syncthreads();
    for (int s = 512; s; s >>= 1) { if (t < s) sh[t] += sh[t + s]; __syncthreads(); }
    float lse = m + logf(sh[0]);
#pragma unroll
    for (int i = 0; i < 32; i++) {
        int j = t + i * 1024;
        if (j < VE) row[j] = v[i] - lse;
    }
}

// ============================ host launcher ==================================
extern "C" void kernel_launch(void* const* d_in, const int* in_sizes, int n_in,
                              void* d_out, int out_size) {
    (void)in_sizes; (void)n_in; (void)out_size;
    const int*           ids      = (const int*)d_in[0];
    const float*         prev_ctx = (const float*)d_in[1];
    const float*         h0       = (const float*)d_in[2];
    const float*         c0       = (const float*)d_in[3];
    const float*         enc      = (const float*)d_in[4];
    const float*         seqs     = (const float*)d_in[5];
    const unsigned char* mask     = (const unsigned char*)d_in[6];
    const int*           ext      = (const int*)d_in[7];
    const float*         embed    = (const float*)d_in[8];
    const float*         W_reduce = (const float*)d_in[9];
    const float*         b_reduce = (const float*)d_in[10];
    const float*         W_key    = (const float*)d_in[11];
    const float*         b_key    = (const float*)d_in[12];
    const float*         W_comb   = (const float*)d_in[13];
    const float*         b_comb   = (const float*)d_in[14];
    const float*         W_seqkey = (const float*)d_in[15];
    const float*         W_ih     = (const float*)d_in[16];
    const float*         W_hh     = (const float*)d_in[17];
    const float*         b_ih     = (const float*)d_in[18];
    const float*         b_hh     = (const float*)d_in[19];
    const float*         W_out    = (const float*)d_in[20];
    const float*         b_out    = (const float*)d_in[21];
    float* out = (float*)d_out;

    void *p_x, *p_gates, *p_cat2, *p_comb;
    cudaGetSymbolAddress(&p_x, g_x);
    cudaGetSymbolAddress(&p_gates, g_gates);
    cudaGetSymbolAddress(&p_cat2, g_cat2);
    cudaGetSymbolAddress(&p_comb, g_comb);

    static int smem_set = 0;
    if (!smem_set) {
        cudaFuncSetAttribute(wout_mma, cudaFuncAttributeMaxDynamicSharedMemorySize, 81920);
        cudaFuncSetAttribute(final_kernel, cudaFuncAttributeMaxDynamicSharedMemorySize, FINAL_SMEM);
        smem_set = 1;
    }

    // 0) init + bf16 conversions
    init_kernel<<<4096, 512>>>(ids, prev_ctx, embed, seqs, W_seqkey, out);
    // 1+2) dual: x = cat @ W_reduce.T + b_reduce  |  gates += h0 @ W_hh.T  (z=16)
    {
        dim3 g((4 * H) / BN, 2, 16);
        gemm_dual<<<g, 256>>>(W_reduce, b_reduce, h0, W_hh);
    }
    // 3) gates += x @ W_ih.T  (z=16)
    {
        dim3 g((4 * H) / BN, 1, 16);
        gemm_sk<<<g, 256>>>((const float*)p_x, EMB, W_ih, EMB,
                            (float*)p_gates, 4 * H, EMB, nullptr);
    }
    // 4) LSTM elementwise + kb (shuffle reduce)
    lstm_kernel<<<B, 512>>>(c0, b_ih, b_hh, b_key, out);
    // 5) seq-key GEMM + tanh + dot(h1) (dominant)
    {
        dim3 g(H / 64, S_SEQ / 64, B);
        seqkey_mma<<<g, 128>>>();
    }
    // 6) key projection
    {
        dim3 g(B, 8);
        keyproj_kernel<<<g, 256>>>(W_key);
    }
    // 7) fused energies + softmax -> attn weights
    energysoftmax_kernel<<<B, 512>>>(enc, out);
    // 8) context (writes g_cat2 + out ctx region directly)
    {
        dim3 g(B, 8);
        context_kernel<<<g, 512>>>(enc, out);
    }
    // 9) comb_pre = cat(h1,ctx) @ W_comb.T + b_comb  (z=16)
    {
        dim3 g(H / BN, 1, 16);
        gemm_sk<<<g, 256>>>((const float*)p_cat2, 1024, W_comb, 1024,
                            (float*)p_comb, H, 1024, b_comb);
    }
    // 10) logits = tanh(comb) @ W_out.T + b_out (tanh folded into A-load)
    wout_mma<<<V / 64, 128, 81920>>>(W_out, b_out, out);
    // 11) smem scatter-max + log_softmax
    final_kernel<<<B, 1024, FINAL_SMEM>>>(out, mask, ext);
}

// round 14
// speedup vs baseline: 1.2051x; 1.2051x over previous
#include <cuda_runtime.h>
#include <cuda_bf16.h>
#include <math.h>

#define B 64
#define H 512
#define EMB 512
#define V 32000
#define S_ENC 512
#define S_SEQ 512
#define ENC2 512
#define OOV 50
#define VE (V + OOV) /* 32050 */
#define NEGINF (-1e12f)
#define BVE ((size_t)B * VE)

// ---------------- scratch (device globals) -----------------------------------
__device__ float    g_cat[B * 1024];
__device__ float    g_x[B * EMB];
__device__ float    g_gates[B * 4 * H];
__device__ float    g_h1[B * H];
__device__ float    g_keyp[B * H];
__device__ float    g_kb[B];
__device__ float    g_energies[B * S_ENC];
__device__ float    g_cat2[B * 1024];
__device__ float    g_comb[B * H];
__device__ float    g_seqE[B * S_SEQ];
__device__ __nv_bfloat16 g_seqs_bf[(size_t)B * S_SEQ * ENC2]; // 33.5MB
__device__ __nv_bfloat16 g_wsk_bf[H * ENC2];                  // 0.5MB

__device__ __forceinline__ float sigmoidf_(float x) { return 1.f / (1.f + expf(-x)); }
__device__ __forceinline__ unsigned ordf(float f) {
    unsigned u = __float_as_uint(f);
    return (u & 0x80000000u) ? ~u : (u | 0x80000000u);
}
__device__ __forceinline__ float iordf(unsigned u) {
    return (u & 0x80000000u) ? __uint_as_float(u ^ 0x80000000u) : __uint_as_float(~u);
}
__device__ __forceinline__ unsigned pack_bf2(float x, float y) {
    __nv_bfloat162 h = __floats2bfloat162_rn(x, y);
    return *reinterpret_cast<unsigned*>(&h);
}
__device__ __forceinline__ unsigned swz(unsigned byte_off) {
    return byte_off ^ ((byte_off >> 3) & 0x70); // 128B-row swizzle
}
// swizzle for 1024B rows: XOR 16B-unit index with (row&7)
__device__ __forceinline__ unsigned swzA(int row, int byteInRow) {
    return (unsigned)(row * 1024 + ((((byteInRow >> 4) ^ (row & 7)) << 4) | (byteInRow & 15)));
}

#define MMA16816(C, A, B0, B1) asm volatile( \
    "mma.sync.aligned.m16n8k16.row.col.f32.bf16.bf16.f32 " \
    "{%0,%1,%2,%3},{%4,%5,%6,%7},{%8,%9},{%0,%1,%2,%3};" \
    : "+f"(C[0]), "+f"(C[1]), "+f"(C[2]), "+f"(C[3]) \
    : "r"(A[0]), "r"(A[1]), "r"(A[2]), "r"(A[3]), "r"(B0), "r"(B1))

#define LDMX4(R, ADDR) asm volatile( \
    "ldmatrix.sync.aligned.m8n8.x4.shared.b16 {%0,%1,%2,%3},[%4];" \
    : "=r"(R[0]), "=r"(R[1]), "=r"(R[2]), "=r"(R[3]) : "r"(ADDR))

// ---------------- init --------------------------------------------------------
__global__ void init_kernel(const int* __restrict__ ids,
                            const float* __restrict__ prev_ctx,
                            const float* __restrict__ embed,
                            const float* __restrict__ seqs,
                            const float* __restrict__ W_seqkey,
                            float* __restrict__ out) {
    int stride = gridDim.x * blockDim.x;
    int i0 = blockIdx.x * blockDim.x + threadIdx.x;
    for (int j = i0; j < B; j += stride) g_kb[j] = 0.f;
    for (int j = i0; j < B * OOV; j += stride) {
        int b = j / OOV, k = j % OOV;
        out[b * VE + V + k] = 0.f;
    }
    for (int j = i0; j < B * S_SEQ; j += stride) g_seqE[j] = 0.f;
    for (int j = i0; j < B * EMB; j += stride) g_x[j] = 0.f;
    for (int j = i0; j < B * 4 * H; j += stride) g_gates[j] = 0.f;
    for (int j = i0; j < B * H; j += stride) {
        g_comb[j] = 0.f;
        out[BVE + j] = 0.f; // ctx region of out (context_kernel atomicAdds here)
    }
    for (int j = i0; j < B * 1024; j += stride) {
        int b = j >> 10, k = j & 1023;
        g_cat[j] = (k < EMB) ? embed[(size_t)ids[b] * EMB + k] : prev_ctx[b * H + (k - EMB)];
        if (k >= 512) g_cat2[j] = 0.f;
    }
    // bf16 conversions (vectorized by 4)
    {
        const size_t n4 = (size_t)B * S_SEQ * ENC2 / 4;
        const float4* src = (const float4*)seqs;
        uint2* dst = (uint2*)g_seqs_bf;
        for (size_t j = i0; j < n4; j += stride) {
            float4 f = src[j];
            dst[j] = make_uint2(pack_bf2(f.x, f.y), pack_bf2(f.z, f.w));
        }
    }
    {
        const size_t n4 = (size_t)H * ENC2 / 4;
        const float4* src = (const float4*)W_seqkey;
        uint2* dst = (uint2*)g_wsk_bf;
        for (size_t j = i0; j < n4; j += stride) {
            float4 f = src[j];
            dst[j] = make_uint2(pack_bf2(f.x, f.y), pack_bf2(f.z, f.w));
        }
    }
}

// ---------------- split-K SIMT GEMM (M=64): atomicAdd epilogue ----------------
#define BM 64
#define BN 64
#define BK 16
__device__ __forceinline__ void gemm_body(const float* __restrict__ A, int lda,
                                          const float* __restrict__ Bw, int ldb,
                                          float* __restrict__ C, int ldc,
                                          int K, int nsplit,
                                          const float* __restrict__ bias) {
    __shared__ float As[BK][BM + 1];
    __shared__ float Bs[BK][BN + 1];
    int tid = threadIdx.x;
    int n0 = blockIdx.x * BN;
    int kslice = K / nsplit;
    int kbeg = blockIdx.z * kslice;
    int tm = (tid / 16) * 4;
    int tn = (tid % 16) * 4;
    float acc[4][4] = {};
    int lrow = tid >> 2;
    int lkc = (tid & 3) * 4;

    for (int k0 = kbeg; k0 < kbeg + kslice; k0 += BK) {
        float4 av = *reinterpret_cast<const float4*>(A + (size_t)lrow * lda + k0 + lkc);
        As[lkc + 0][lrow] = av.x; As[lkc + 1][lrow] = av.y;
        As[lkc + 2][lrow] = av.z; As[lkc + 3][lrow] = av.w;
        float4 bv = *reinterpret_cast<const float4*>(Bw + (size_t)(n0 + lrow) * ldb + k0 + lkc);
        Bs[lkc + 0][lrow] = bv.x; Bs[lkc + 1][lrow] = bv.y;
        Bs[lkc + 2][lrow] = bv.z; Bs[lkc + 3][lrow] = bv.w;
        __syncthreads();
#pragma unroll
        for (int kk = 0; kk < BK; ++kk) {
            float a0 = As[kk][tm + 0], a1 = As[kk][tm + 1];
            float a2 = As[kk][tm + 2], a3 = As[kk][tm + 3];
            float b0 = Bs[kk][tn + 0], b1 = Bs[kk][tn + 1];
            float b2 = Bs[kk][tn + 2], b3 = Bs[kk][tn + 3];
            acc[0][0] += a0 * b0; acc[0][1] += a0 * b1; acc[0][2] += a0 * b2; acc[0][3] += a0 * b3;
            acc[1][0] += a1 * b0; acc[1][1] += a1 * b1; acc[1][2] += a1 * b2; acc[1][3] += a1 * b3;
            acc[2][0] += a2 * b0; acc[2][1] += a2 * b1; acc[2][2] += a2 * b2; acc[2][3] += a2 * b3;
            acc[3][0] += a3 * b0; acc[3][1] += a3 * b1; acc[3][2] += a3 * b2; acc[3][3] += a3 * b3;
        }
        __syncthreads();
    }
#pragma unroll
    for (int i = 0; i < 4; i++)
#pragma unroll
        for (int j = 0; j < 4; j++) {
            int cgl = n0 + tn + j;
            float v = acc[i][j];
            if (bias && blockIdx.z == 0) v += bias[cgl];
            atomicAdd(C + (size_t)(tm + i) * ldc + cgl, v);
        }
}

__global__ void gemm_sk(const float* __restrict__ A, int lda,
                        const float* __restrict__ Bw, int ldb,
                        float* __restrict__ C, int ldc,
                        int K, const float* __restrict__ bias) {
    gemm_body(A, lda, Bw, ldb, C, ldc, K, gridDim.z, bias);
}

__global__ void gemm_dual(const float* __restrict__ Wr,
                          const float* __restrict__ br,
                          const float* __restrict__ h0,
                          const float* __restrict__ Whh) {
    if (blockIdx.y == 0) {
        if (blockIdx.x >= EMB / BN) return;
        gemm_body(g_cat, 1024, Wr, 1024, g_x, EMB, 1024, gridDim.z, br);
    } else {
        gemm_body(h0, H, Whh, H, g_gates, 4 * H, H, gridDim.z, nullptr);
    }
}

// ---------------- LSTM elementwise + kb reduction (shuffle + atomic) -----------
__global__ void __launch_bounds__(512) lstm_kernel(
    const float* __restrict__ c0, const float* __restrict__ b_ih,
    const float* __restrict__ b_hh, const float* __restrict__ b_key,
    float* __restrict__ out) {
    int b = blockIdx.x, h = threadIdx.x;
    const float* gr = g_gates + b * 4 * H;
    float ig = sigmoidf_(gr[h] + b_ih[h] + b_hh[h]);
    float fg = sigmoidf_(gr[H + h] + b_ih[H + h] + b_hh[H + h]);
    float gg = tanhf(gr[2 * H + h] + b_ih[2 * H + h] + b_hh[2 * H + h]);
    float og = sigmoidf_(gr[3 * H + h] + b_ih[3 * H + h] + b_hh[3 * H + h]);
    float c1 = fg * c0[b * H + h] + ig * gg;
    float h1 = og * tanhf(c1);
    g_h1[b * H + h] = h1;
    g_cat2[b * 1024 + h] = h1;
    out[BVE + B * H + b * H + h] = h1;
    out[BVE + 2 * B * H + b * H + h] = c1;
    float val = b_key[h] * h1;
    for (int o = 16; o; o >>= 1) val += __shfl_down_sync(0xffffffffu, val, o);
    if ((h & 31) == 0) atomicAdd(&g_kb[b], val);
}

// ---------------- key projection ------------------------------------------------
__global__ void __launch_bounds__(256) keyproj_kernel(const float* __restrict__ W_key) {
    int b = blockIdx.x, nc = blockIdx.y;
    int t = threadIdx.x;
    __shared__ float hs[H];
    __shared__ float part[4][64];
    hs[t] = g_h1[b * H + t];
    hs[t + 256] = g_h1[b * H + t + 256];
    __syncthreads();
    int n = nc * 64 + (t & 63);
    int hp = t >> 6;
    const float* wp = W_key + (size_t)(hp * 128) * H + n;
    const float* hh = hs + hp * 128;
    float acc = 0.f;
#pragma unroll 16
    for (int k = 0; k < 128; k++) acc += hh[k] * wp[(size_t)k * H];
    part[hp][t & 63] = acc;
    __syncthreads();
    if (t < 64)
        g_keyp[b * H + nc * 64 + t] = part[0][t] + part[1][t] + part[2][t] + part[3][t];
}

// ---------------- energies / softmax / context ---------------------------------
__global__ void energies_kernel(const float* __restrict__ enc) {
    int gw = (blockIdx.x * blockDim.x + threadIdx.x) >> 5;
    int lane = threadIdx.x & 31;
    if (gw >= B * S_ENC) return;
    int b = gw / S_ENC;
    const float* er = enc + (size_t)gw * H;
    const float* kp = g_keyp + b * H;
    float e = 0.f, sm = 0.f;
#pragma unroll 4
    for (int k = lane; k < H; k += 32) {
        float x = er[k];
        e += x * kp[k];
        sm += x;
    }
    for (int o = 16; o; o >>= 1) {
        e += __shfl_down_sync(0xffffffffu, e, o);
        sm += __shfl_down_sync(0xffffffffu, sm, o);
    }
    if (lane == 0) g_energies[gw] = (sm == 0.f) ? 1e-12f : (e + g_kb[b]);
}

__global__ void attnsoftmax_kernel(float* __restrict__ out) {
    int b = blockIdx.x, t = threadIdx.x;
    __shared__ float sh[S_ENC];
    float e = g_energies[b * S_ENC + t];
    sh[t] = e;
    __syncthreads();
    for (int s = 256; s; s >>= 1) { if (t < s) sh[t] = fmaxf(sh[t], sh[t + s]); __syncthreads(); }
    float m = sh[0];
    __syncthreads();
    float ex = expf(e - m);
    sh[t] = ex;
    __syncthreads();
    for (int s = 256; s; s >>= 1) { if (t < s) sh[t] += sh[t + s]; __syncthreads(); }
    float w = ex / sh[0];
    g_energies[b * S_ENC + t] = w;
    out[BVE + 3 * B * H + b * S_ENC + t] = w;
}

// context: accumulates into g_cat2 AND directly into out ctx region (init zeroed)
__global__ void context_kernel(const float* __restrict__ enc, float* __restrict__ out) {
    int b = blockIdx.x, chunk = blockIdx.y, h = threadIdx.x;
    int s0 = chunk * 64;
    const float* w = g_energies + b * S_ENC;
    const float* er = enc + ((size_t)b * S_ENC + s0) * H + h;
    float acc = 0.f;
#pragma unroll 4
    for (int s = 0; s < 64; s++) acc += w[s0 + s] * er[(size_t)s * H];
    atomicAdd(&g_cat2[b * 1024 + 512 + h], acc);
    atomicAdd(&out[BVE + b * H + h], acc);
}

// ---------------- W_out MMA: A = tanh(g_comb) converted in-kernel --------------
__global__ void __launch_bounds__(128) wout_mma(const float* __restrict__ W_out,
                                                const float* __restrict__ b_out,
                                                float* __restrict__ out) {
    extern __shared__ char dynsm[];
    char* smA = dynsm;              // 65536
    char* smB = dynsm + 65536;      // 2 * 8192
    int tid = threadIdx.x;
    int warp = tid >> 5, lane = tid & 31;
    int wm = warp & 1, wn = warp >> 1;
    int n0 = blockIdx.x * 64;
    unsigned a_base = (unsigned)__cvta_generic_to_shared(smA);
    unsigned b_base = (unsigned)__cvta_generic_to_shared(smB);
    int lrow = lane & 15, lk = (lane >> 4) * 8;

    // load full A: tanh(g_comb) fp32 -> bf16 swizzled smem (64x512)
#pragma unroll
    for (int i = 0; i < 32; i++) {
        int ch = i * 128 + tid;
        int r = ch >> 6, c = ch & 63;
        const float* src = g_comb + r * H + c * 8;
        float4 f0 = *(const float4*)(src);
        float4 f1 = *(const float4*)(src + 4);
        uint4 v;
        v.x = pack_bf2(tanhf(f0.x), tanhf(f0.y));
        v.y = pack_bf2(tanhf(f0.z), tanhf(f0.w));
        v.z = pack_bf2(tanhf(f1.x), tanhf(f1.y));
        v.w = pack_bf2(tanhf(f1.z), tanhf(f1.w));
        *(uint4*)(smA + swzA(r, c * 16)) = v;
    }

    float acc[2][4][4] = {};
    float4 f[4][2];
#pragma unroll
    for (int i = 0; i < 4; i++) {
        int ch = i * 128 + tid, r = ch >> 3, c = ch & 7;
        const float* src = W_out + (size_t)(n0 + r) * H + c * 8;
        f[i][0] = *(const float4*)(src);
        f[i][1] = *(const float4*)(src + 4);
    }
    for (int kc = 0; kc < H / 64; kc++) {
        char* buf = smB + (kc & 1) * 8192;
#pragma unroll
        for (int i = 0; i < 4; i++) {
            int ch = i * 128 + tid, r = ch >> 3, c = ch & 7;
            uint4 v;
            v.x = pack_bf2(f[i][0].x, f[i][0].y);
            v.y = pack_bf2(f[i][0].z, f[i][0].w);
            v.z = pack_bf2(f[i][1].x, f[i][1].y);
            v.w = pack_bf2(f[i][1].z, f[i][1].w);
            *(uint4*)(buf + swz(r * 128 + c * 16)) = v;
        }
        __syncthreads();
        if (kc + 1 < H / 64) {
            int k0 = (kc + 1) * 64;
#pragma unroll
            for (int i = 0; i < 4; i++) {
                int ch = i * 128 + tid, r = ch >> 3, c = ch & 7;
                const float* src = W_out + (size_t)(n0 + r) * H + k0 + c * 8;
                f[i][0] = *(const float4*)(src);
                f[i][1] = *(const float4*)(src + 4);
            }
        }
        unsigned bbuf = b_base + (kc & 1) * 8192;
#pragma unroll
        for (int ks = 0; ks < 4; ks++) {
            unsigned af[2][4], bfm[2][4];
#pragma unroll
            for (int mf = 0; mf < 2; mf++) {
                int row = wm * 32 + mf * 16 + lrow;
                LDMX4(af[mf], a_base + swzA(row, (kc * 64 + ks * 16 + lk) * 2));
            }
#pragma unroll
            for (int nh = 0; nh < 2; nh++) {
                int row = wn * 32 + nh * 16 + lrow;
                LDMX4(bfm[nh], bbuf + swz(row * 128 + (ks * 16 + lk) * 2));
            }
#pragma unroll
            for (int mf = 0; mf < 2; mf++)
#pragma unroll
                for (int nf = 0; nf < 4; nf++) {
                    int nh = nf >> 1, nl = nf & 1;
                    MMA16816(acc[mf][nf], af[mf], bfm[nh][nl], bfm[nh][nl + 2]);
                }
        }
    }
    int qr = lane >> 2, qc = lane & 3;
#pragma unroll
    for (int mf = 0; mf < 2; mf++) {
        int m0 = wm * 32 + mf * 16 + qr;
#pragma unroll
        for (int nf = 0; nf < 4; nf++) {
            int n = n0 + wn * 32 + nf * 8 + qc * 2;
            float bo0 = b_out[n], bo1 = b_out[n + 1];
            out[(size_t)m0 * VE + n]           = acc[mf][nf][0] + bo0;
            out[(size_t)m0 * VE + n + 1]       = acc[mf][nf][1] + bo1;
            out[(size_t)(m0 + 8) * VE + n]     = acc[mf][nf][2] + bo0;
            out[(size_t)(m0 + 8) * VE + n + 1] = acc[mf][nf][3] + bo1;
        }
    }
}

// ---------------- tensor-core seqkey (R5/R9 structure, bf16 A) -----------------
__global__ void __launch_bounds__(128) seqkey_mma() {
    __shared__ __align__(128) __nv_bfloat16 As[64 * 64];
    __shared__ __align__(128) __nv_bfloat16 Bs[64 * 64];
    int tid = threadIdx.x;
    int warp = tid >> 5, lane = tid & 31;
    int wm = warp & 1, wn = warp >> 1;
    int n0 = blockIdx.x * 64, s0 = blockIdx.y * 64, b = blockIdx.z;
    const __nv_bfloat16* Ag = g_seqs_bf + ((size_t)b * S_SEQ + s0) * ENC2;
    const __nv_bfloat16* Bg = g_wsk_bf + (size_t)n0 * ENC2;

    float acc[2][4][4] = {};
    unsigned a_base = (unsigned)__cvta_generic_to_shared(As);
    unsigned b_base = (unsigned)__cvta_generic_to_shared(Bs);
    int lrow = lane & 15, lk = (lane >> 4) * 8;

    uint4 pa[4], pb[4];
#pragma unroll
    for (int i = 0; i < 4; i++) {
        int ch = i * 128 + tid, r = ch >> 3, c = ch & 7;
        pa[i] = *(const uint4*)(Ag + (size_t)r * ENC2 + c * 8);
        pb[i] = *(const uint4*)(Bg + (size_t)r * ENC2 + c * 8);
    }
    for (int kc = 0; kc < ENC2 / 64; kc++) {
#pragma unroll
        for (int i = 0; i < 4; i++) {
            int ch = i * 128 + tid, r = ch >> 3, c = ch & 7;
            unsigned off = swz(r * 128 + c * 16);
            *(uint4*)((char*)As + off) = pa[i];
            *(uint4*)((char*)Bs + off) = pb[i];
        }
        __syncthreads();
        if (kc + 1 < ENC2 / 64) {
            int k0 = (kc + 1) * 64;
#pragma unroll
            for (int i = 0; i < 4; i++) {
                int ch = i * 128 + tid, r = ch >> 3, c = ch & 7;
                pa[i] = *(const uint4*)(Ag + (size_t)r * ENC2 + k0 + c * 8);
                pb[i] = *(const uint4*)(Bg + (size_t)r * ENC2 + k0 + c * 8);
            }
        }
#pragma unroll
        for (int ks = 0; ks < 4; ks++) {
            int kb = ks * 16;
            unsigned af[2][4], bfm[2][4];
#pragma unroll
            for (int mf = 0; mf < 2; mf++) {
                int row = wm * 32 + mf * 16 + lrow;
                LDMX4(af[mf], a_base + swz(row * 128 + (kb + lk) * 2));
            }
#pragma unroll
            for (int nh = 0; nh < 2; nh++) {
                int row = wn * 32 + nh * 16 + lrow;
                LDMX4(bfm[nh], b_base + swz(row * 128 + (kb + lk) * 2));
            }
#pragma unroll
            for (int mf = 0; mf < 2; mf++)
#pragma unroll
                for (int nf = 0; nf < 4; nf++) {
                    int nh = nf >> 1, nl = nf & 1;
                    MMA16816(acc[mf][nf], af[mf], bfm[nh][nl], bfm[nh][nl + 2]);
                }
        }
        __syncthreads();
    }
    const float* h1p = g_h1 + b * H + n0 + wn * 32;
    int qr = lane >> 2, qc = lane & 3;
#pragma unroll
    for (int mf = 0; mf < 2; mf++) {
        float s0v = 0.f, s1v = 0.f;
#pragma unroll
        for (int nf = 0; nf < 4; nf++) {
            float h0v = h1p[nf * 8 + qc * 2 + 0];
            float h1v = h1p[nf * 8 + qc * 2 + 1];
            s0v += tanhf(acc[mf][nf][0]) * h0v + tanhf(acc[mf][nf][1]) * h1v;
            s1v += tanhf(acc[mf][nf][2]) * h0v + tanhf(acc[mf][nf][3]) * h1v;
        }
        s0v += __shfl_xor_sync(0xffffffffu, s0v, 1);
        s0v += __shfl_xor_sync(0xffffffffu, s0v, 2);
        s1v += __shfl_xor_sync(0xffffffffu, s1v, 1);
        s1v += __shfl_xor_sync(0xffffffffu, s1v, 2);
        if (qc == 0) {
            int srow = s0 + wm * 32 + mf * 16 + qr;
            atomicAdd(&g_seqE[b * S_SEQ + srow], s0v);
            atomicAdd(&g_seqE[b * S_SEQ + srow + 8], s1v);
        }
    }
}

// ---------------- final: smem scatter-max + register-cached log_softmax --------
#define FINAL_SMEM (VE * 4 + 1024 * 4)
__global__ void __launch_bounds__(1024) final_kernel(float* __restrict__ out,
                                                     const unsigned char* __restrict__ mask,
                                                     const int* __restrict__ ext) {
    extern __shared__ char dynsm[];
    unsigned* copy_s = (unsigned*)dynsm;
    float* sh = (float*)(dynsm + VE * 4);
    int b = blockIdx.x, t = threadIdx.x;
    unsigned negord = ordf(NEGINF);
    for (int j = t; j < VE; j += 1024) copy_s[j] = negord;
    __syncthreads();
    if (t < 512) {
        float e = mask[b * S_SEQ + t] ? 1e-12f : g_seqE[b * S_SEQ + t];
        atomicMax(&copy_s[ext[b * S_SEQ + t]], ordf(e));
    }
    __syncthreads();
    float* row = out + (size_t)b * VE;
    float v[32];
    float mx = -INFINITY;
#pragma unroll
    for (int i = 0; i < 32; i++) {
        int j = t + i * 1024;
        if (j < VE) {
            float lg = row[j];
            float cf = iordf(copy_s[j]);
            if (cf == NEGINF) cf = 0.f;
            float val = lg + cf;
            if (val == 0.f) val = NEGINF;
            v[i] = val;
            mx = fmaxf(mx, val);
        } else {
            v[i] = NEGINF;
        }
    }
    sh[t] = mx;
    __syncthreads();
    for (int s = 512; s; s >>= 1) { if (t < s) sh[t] = fmaxf(sh[t], sh[t + s]); __syncthreads(); }
    float m = sh[0];
    __syncthreads();
    float sum = 0.f;
#pragma unroll
    for (int i = 0; i < 32; i++) sum += expf(v[i] - m);
    sh[t] = sum;
    __syncthreads();
    for (int s = 512; s; s >>= 1) { if (t < s) sh[t] += sh[t + s]; __syncthreads(); }
    float lse = m + logf(sh[0]);
#pragma unroll
    for (int i = 0; i < 32; i++) {
        int j = t + i * 1024;
        if (j < VE) row[j] = v[i] - lse;
    }
}

// ============================ host launcher ==================================
extern "C" void kernel_launch(void* const* d_in, const int* in_sizes, int n_in,
                              void* d_out, int out_size) {
    (void)in_sizes; (void)n_in; (void)out_size;
    const int*           ids      = (const int*)d_in[0];
    const float*         prev_ctx = (const float*)d_in[1];
    const float*         h0       = (const float*)d_in[2];
    const float*         c0       = (const float*)d_in[3];
    const float*         enc      = (const float*)d_in[4];
    const float*         seqs     = (const float*)d_in[5];
    const unsigned char* mask     = (const unsigned char*)d_in[6];
    const int*           ext      = (const int*)d_in[7];
    const float*         embed    = (const float*)d_in[8];
    const float*         W_reduce = (const float*)d_in[9];
    const float*         b_reduce = (const float*)d_in[10];
    const float*         W_key    = (const float*)d_in[11];
    const float*         b_key    = (const float*)d_in[12];
    const float*         W_comb   = (const float*)d_in[13];
    const float*         b_comb   = (const float*)d_in[14];
    const float*         W_seqkey = (const float*)d_in[15];
    const float*         W_ih     = (const float*)d_in[16];
    const float*         W_hh     = (const float*)d_in[17];
    const float*         b_ih     = (const float*)d_in[18];
    const float*         b_hh     = (const float*)d_in[19];
    const float*         W_out    = (const float*)d_in[20];
    const float*         b_out    = (const float*)d_in[21];
    float* out = (float*)d_out;

    void *p_x, *p_gates, *p_cat2, *p_comb;
    cudaGetSymbolAddress(&p_x, g_x);
    cudaGetSymbolAddress(&p_gates, g_gates);
    cudaGetSymbolAddress(&p_cat2, g_cat2);
    cudaGetSymbolAddress(&p_comb, g_comb);

    static int smem_set = 0;
    if (!smem_set) {
        cudaFuncSetAttribute(wout_mma, cudaFuncAttributeMaxDynamicSharedMemorySize, 81920);
        cudaFuncSetAttribute(final_kernel, cudaFuncAttributeMaxDynamicSharedMemorySize, FINAL_SMEM);
        smem_set = 1;
    }

    // 0) init + bf16 conversions
    init_kernel<<<4096, 512>>>(ids, prev_ctx, embed, seqs, W_seqkey, out);
    // 1+2) dual: x = cat @ W_reduce.T + b_reduce  |  gates += h0 @ W_hh.T  (z=16)
    {
        dim3 g((4 * H) / BN, 2, 16);
        gemm_dual<<<g, 256>>>(W_reduce, b_reduce, h0, W_hh);
    }
    // 3) gates += x @ W_ih.T  (z=16)
    {
        dim3 g((4 * H) / BN, 1, 16);
        gemm_sk<<<g, 256>>>((const float*)p_x, EMB, W_ih, EMB,
                            (float*)p_gates, 4 * H, EMB, nullptr);
    }
    // 4) LSTM elementwise + kb (shuffle reduce)
    lstm_kernel<<<B, 512>>>(c0, b_ih, b_hh, b_key, out);
    // 5) seq-key GEMM + tanh + dot(h1) (dominant)
    {
        dim3 g(H / 64, S_SEQ / 64, B);
        seqkey_mma<<<g, 128>>>();
    }
    // 6) key projection
    {
        dim3 g(B, 8);
        keyproj_kernel<<<g, 256>>>(W_key);
    }
    // 7) energies (full-chip grid — DRAM streaming)
    energies_kernel<<<(B * S_ENC * 32) / 256, 256>>>(enc);
    // 8) softmax -> attn weights
    attnsoftmax_kernel<<<B, S_ENC>>>(out);
    // 9) context (writes g_cat2 + out ctx region directly)
    {
        dim3 g(B, 8);
        context_kernel<<<g, 512>>>(enc, out);
    }
    // 10) comb_pre = cat(h1,ctx) @ W_comb.T + b_comb  (z=16)
    {
        dim3 g(H / BN, 1, 16);
        gemm_sk<<<g, 256>>>((const float*)p_cat2, 1024, W_comb, 1024,
                            (float*)p_comb, H, 1024, b_comb);
    }
    // 11) logits = tanh(comb) @ W_out.T + b_out (tanh folded into A-load)
    wout_mma<<<V / 64, 128, 81920>>>(W_out, b_out, out);
    // 12) smem scatter-max + log_softmax
    final_kernel<<<B, 1024, FINAL_SMEM>>>(out, mask, ext);
}

// round 15
// speedup vs baseline: 1.2077x; 1.0022x over previous
#include <cuda_runtime.h>
#include <cuda_bf16.h>
#include <math.h>

#define B 64
#define H 512
#define EMB 512
#define V 32000
#define S_ENC 512
#define S_SEQ 512
#define ENC2 512
#define OOV 50
#define VE (V + OOV) /* 32050 */
#define NEGINF (-1e12f)
#define BVE ((size_t)B * VE)

// ---------------- scratch (device globals) -----------------------------------
__device__ float    g_cat[B * 1024];
__device__ float    g_x[B * EMB];
__device__ float    g_gates[B * 4 * H];
__device__ float    g_h1[B * H];
__device__ float    g_keyp[B * H];
__device__ float    g_kb[B];
__device__ float    g_energies[B * S_ENC];
__device__ float    g_cat2[B * 1024];
__device__ float    g_comb[B * H];
__device__ float    g_seqE[B * S_SEQ];
__device__ __nv_bfloat16 g_seqs_bf[(size_t)B * S_SEQ * ENC2]; // 33.5MB
__device__ __nv_bfloat16 g_wsk_bf[H * ENC2];                  // 0.5MB

__device__ __forceinline__ float sigmoidf_(float x) { return 1.f / (1.f + expf(-x)); }
__device__ __forceinline__ unsigned ordf(float f) {
    unsigned u = __float_as_uint(f);
    return (u & 0x80000000u) ? ~u : (u | 0x80000000u);
}
__device__ __forceinline__ float iordf(unsigned u) {
    return (u & 0x80000000u) ? __uint_as_float(u ^ 0x80000000u) : __uint_as_float(~u);
}
__device__ __forceinline__ unsigned pack_bf2(float x, float y) {
    __nv_bfloat162 h = __floats2bfloat162_rn(x, y);
    return *reinterpret_cast<unsigned*>(&h);
}
__device__ __forceinline__ unsigned swz(unsigned byte_off) {
    return byte_off ^ ((byte_off >> 3) & 0x70); // 128B-row swizzle
}
// swizzle for 1024B rows: XOR 16B-unit index with (row&7)
__device__ __forceinline__ unsigned swzA(int row, int byteInRow) {
    return (unsigned)(row * 1024 + ((((byteInRow >> 4) ^ (row & 7)) << 4) | (byteInRow & 15)));
}

#define MMA16816(C, A, B0, B1) asm volatile( \
    "mma.sync.aligned.m16n8k16.row.col.f32.bf16.bf16.f32 " \
    "{%0,%1,%2,%3},{%4,%5,%6,%7},{%8,%9},{%0,%1,%2,%3};" \
    : "+f"(C[0]), "+f"(C[1]), "+f"(C[2]), "+f"(C[3]) \
    : "r"(A[0]), "r"(A[1]), "r"(A[2]), "r"(A[3]), "r"(B0), "r"(B1))

#define LDMX4(R, ADDR) asm volatile( \
    "ldmatrix.sync.aligned.m8n8.x4.shared.b16 {%0,%1,%2,%3},[%4];" \
    : "=r"(R[0]), "=r"(R[1]), "=r"(R[2]), "=r"(R[3]) : "r"(ADDR))

// ---------------- init --------------------------------------------------------
__global__ void init_kernel(const int* __restrict__ ids,
                            const float* __restrict__ prev_ctx,
                            const float* __restrict__ embed,
                            const float* __restrict__ seqs,
                            const float* __restrict__ W_seqkey,
                            float* __restrict__ out) {
    int stride = gridDim.x * blockDim.x;
    int i0 = blockIdx.x * blockDim.x + threadIdx.x;
    for (int j = i0; j < B; j += stride) g_kb[j] = 0.f;
    for (int j = i0; j < B * OOV; j += stride) {
        int b = j / OOV, k = j % OOV;
        out[b * VE + V + k] = 0.f;
    }
    for (int j = i0; j < B * S_SEQ; j += stride) g_seqE[j] = 0.f;
    for (int j = i0; j < B * EMB; j += stride) g_x[j] = 0.f;
    for (int j = i0; j < B * 4 * H; j += stride) g_gates[j] = 0.f;
    for (int j = i0; j < B * H; j += stride) {
        g_comb[j] = 0.f;
        out[BVE + j] = 0.f; // ctx region of out (context_kernel atomicAdds here)
    }
    for (int j = i0; j < B * 1024; j += stride) {
        int b = j >> 10, k = j & 1023;
        g_cat[j] = (k < EMB) ? embed[(size_t)ids[b] * EMB + k] : prev_ctx[b * H + (k - EMB)];
        if (k >= 512) g_cat2[j] = 0.f;
    }
    // bf16 conversions (vectorized by 4)
    {
        const size_t n4 = (size_t)B * S_SEQ * ENC2 / 4;
        const float4* src = (const float4*)seqs;
        uint2* dst = (uint2*)g_seqs_bf;
        for (size_t j = i0; j < n4; j += stride) {
            float4 f = src[j];
            dst[j] = make_uint2(pack_bf2(f.x, f.y), pack_bf2(f.z, f.w));
        }
    }
    {
        const size_t n4 = (size_t)H * ENC2 / 4;
        const float4* src = (const float4*)W_seqkey;
        uint2* dst = (uint2*)g_wsk_bf;
        for (size_t j = i0; j < n4; j += stride) {
            float4 f = src[j];
            dst[j] = make_uint2(pack_bf2(f.x, f.y), pack_bf2(f.z, f.w));
        }
    }
}

// ---------------- split-K SIMT GEMM (M=64): atomicAdd epilogue ----------------
#define BM 64
#define BN 64
#define BK 16
__device__ __forceinline__ void gemm_body(const float* __restrict__ A, int lda,
                                          const float* __restrict__ Bw, int ldb,
                                          float* __restrict__ C, int ldc,
                                          int K, int nsplit,
                                          const float* __restrict__ bias) {
    __shared__ float As[BK][BM + 1];
    __shared__ float Bs[BK][BN + 1];
    int tid = threadIdx.x;
    int n0 = blockIdx.x * BN;
    int kslice = K / nsplit;
    int kbeg = blockIdx.z * kslice;
    int tm = (tid / 16) * 4;
    int tn = (tid % 16) * 4;
    float acc[4][4] = {};
    int lrow = tid >> 2;
    int lkc = (tid & 3) * 4;

    for (int k0 = kbeg; k0 < kbeg + kslice; k0 += BK) {
        float4 av = *reinterpret_cast<const float4*>(A + (size_t)lrow * lda + k0 + lkc);
        As[lkc + 0][lrow] = av.x; As[lkc + 1][lrow] = av.y;
        As[lkc + 2][lrow] = av.z; As[lkc + 3][lrow] = av.w;
        float4 bv = *reinterpret_cast<const float4*>(Bw + (size_t)(n0 + lrow) * ldb + k0 + lkc);
        Bs[lkc + 0][lrow] = bv.x; Bs[lkc + 1][lrow] = bv.y;
        Bs[lkc + 2][lrow] = bv.z; Bs[lkc + 3][lrow] = bv.w;
        __syncthreads();
#pragma unroll
        for (int kk = 0; kk < BK; ++kk) {
            float a0 = As[kk][tm + 0], a1 = As[kk][tm + 1];
            float a2 = As[kk][tm + 2], a3 = As[kk][tm + 3];
            float b0 = Bs[kk][tn + 0], b1 = Bs[kk][tn + 1];
            float b2 = Bs[kk][tn + 2], b3 = Bs[kk][tn + 3];
            acc[0][0] += a0 * b0; acc[0][1] += a0 * b1; acc[0][2] += a0 * b2; acc[0][3] += a0 * b3;
            acc[1][0] += a1 * b0; acc[1][1] += a1 * b1; acc[1][2] += a1 * b2; acc[1][3] += a1 * b3;
            acc[2][0] += a2 * b0; acc[2][1] += a2 * b1; acc[2][2] += a2 * b2; acc[2][3] += a2 * b3;
            acc[3][0] += a3 * b0; acc[3][1] += a3 * b1; acc[3][2] += a3 * b2; acc[3][3] += a3 * b3;
        }
        __syncthreads();
    }
#pragma unroll
    for (int i = 0; i < 4; i++)
#pragma unroll
        for (int j = 0; j < 4; j++) {
            int cgl = n0 + tn + j;
            float v = acc[i][j];
            if (bias && blockIdx.z == 0) v += bias[cgl];
            atomicAdd(C + (size_t)(tm + i) * ldc + cgl, v);
        }
}

__global__ void gemm_sk(const float* __restrict__ A, int lda,
                        const float* __restrict__ Bw, int ldb,
                        float* __restrict__ C, int ldc,
                        int K, const float* __restrict__ bias) {
    gemm_body(A, lda, Bw, ldb, C, ldc, K, gridDim.z, bias);
}

__global__ void gemm_dual(const float* __restrict__ Wr,
                          const float* __restrict__ br,
                          const float* __restrict__ h0,
                          const float* __restrict__ Whh) {
    if (blockIdx.y == 0) {
        if (blockIdx.x >= EMB / BN) return;
        gemm_body(g_cat, 1024, Wr, 1024, g_x, EMB, 1024, gridDim.z, br);
    } else {
        gemm_body(h0, H, Whh, H, g_gates, 4 * H, H, gridDim.z, nullptr);
    }
}

// ---------------- LSTM elementwise + kb (grid B x 4, 128 thr) ------------------
__global__ void __launch_bounds__(128) lstm_kernel(
    const float* __restrict__ c0, const float* __restrict__ b_ih,
    const float* __restrict__ b_hh, const float* __restrict__ b_key,
    float* __restrict__ out) {
    int b = blockIdx.x;
    int h = blockIdx.y * 128 + threadIdx.x;
    const float* gr = g_gates + b * 4 * H;
    float ig = sigmoidf_(gr[h] + b_ih[h] + b_hh[h]);
    float fg = sigmoidf_(gr[H + h] + b_ih[H + h] + b_hh[H + h]);
    float gg = tanhf(gr[2 * H + h] + b_ih[2 * H + h] + b_hh[2 * H + h]);
    float og = sigmoidf_(gr[3 * H + h] + b_ih[3 * H + h] + b_hh[3 * H + h]);
    float c1 = fg * c0[b * H + h] + ig * gg;
    float h1 = og * tanhf(c1);
    g_h1[b * H + h] = h1;
    g_cat2[b * 1024 + h] = h1;
    out[BVE + B * H + b * H + h] = h1;
    out[BVE + 2 * B * H + b * H + h] = c1;
    float val = b_key[h] * h1;
    for (int o = 16; o; o >>= 1) val += __shfl_down_sync(0xffffffffu, val, o);
    if ((threadIdx.x & 31) == 0) atomicAdd(&g_kb[b], val);
}

// ---------------- key projection ------------------------------------------------
__global__ void __launch_bounds__(256) keyproj_kernel(const float* __restrict__ W_key) {
    int b = blockIdx.x, nc = blockIdx.y;
    int t = threadIdx.x;
    __shared__ float hs[H];
    __shared__ float part[4][64];
    hs[t] = g_h1[b * H + t];
    hs[t + 256] = g_h1[b * H + t + 256];
    __syncthreads();
    int n = nc * 64 + (t & 63);
    int hp = t >> 6;
    const float* wp = W_key + (size_t)(hp * 128) * H + n;
    const float* hh = hs + hp * 128;
    float acc = 0.f;
#pragma unroll 16
    for (int k = 0; k < 128; k++) acc += hh[k] * wp[(size_t)k * H];
    part[hp][t & 63] = acc;
    __syncthreads();
    if (t < 64)
        g_keyp[b * H + nc * 64 + t] = part[0][t] + part[1][t] + part[2][t] + part[3][t];
}

// ---------------- energies / softmax / context ---------------------------------
__global__ void energies_kernel(const float* __restrict__ enc) {
    int gw = (blockIdx.x * blockDim.x + threadIdx.x) >> 5;
    int lane = threadIdx.x & 31;
    if (gw >= B * S_ENC) return;
    int b = gw / S_ENC;
    const float* er = enc + (size_t)gw * H;
    const float* kp = g_keyp + b * H;
    float e = 0.f, sm = 0.f;
#pragma unroll 4
    for (int k = lane; k < H; k += 32) {
        float x = er[k];
        e += x * kp[k];
        sm += x;
    }
    for (int o = 16; o; o >>= 1) {
        e += __shfl_down_sync(0xffffffffu, e, o);
        sm += __shfl_down_sync(0xffffffffu, sm, o);
    }
    if (lane == 0) g_energies[gw] = (sm == 0.f) ? 1e-12f : (e + g_kb[b]);
}

__global__ void attnsoftmax_kernel(float* __restrict__ out) {
    int b = blockIdx.x, t = threadIdx.x;
    __shared__ float sh[S_ENC];
    float e = g_energies[b * S_ENC + t];
    sh[t] = e;
    __syncthreads();
    for (int s = 256; s; s >>= 1) { if (t < s) sh[t] = fmaxf(sh[t], sh[t + s]); __syncthreads(); }
    float m = sh[0];
    __syncthreads();
    float ex = expf(e - m);
    sh[t] = ex;
    __syncthreads();
    for (int s = 256; s; s >>= 1) { if (t < s) sh[t] += sh[t + s]; __syncthreads(); }
    float w = ex / sh[0];
    g_energies[b * S_ENC + t] = w;
    out[BVE + 3 * B * H + b * S_ENC + t] = w;
}

// context: accumulates into g_cat2 AND directly into out ctx region (init zeroed)
__global__ void context_kernel(const float* __restrict__ enc, float* __restrict__ out) {
    int b = blockIdx.x, chunk = blockIdx.y, h = threadIdx.x;
    int s0 = chunk * 64;
    const float* w = g_energies + b * S_ENC;
    const float* er = enc + ((size_t)b * S_ENC + s0) * H + h;
    float acc = 0.f;
#pragma unroll 4
    for (int s = 0; s < 64; s++) acc += w[s0 + s] * er[(size_t)s * H];
    atomicAdd(&g_cat2[b * 1024 + 512 + h], acc);
    atomicAdd(&out[BVE + b * H + h], acc);
}

// ---------------- W_out MMA: A = tanh(g_comb) converted in-kernel --------------
__global__ void __launch_bounds__(128) wout_mma(const float* __restrict__ W_out,
                                                const float* __restrict__ b_out,
                                                float* __restrict__ out) {
    extern __shared__ char dynsm[];
    char* smA = dynsm;              // 65536
    char* smB = dynsm + 65536;      // 2 * 8192
    int tid = threadIdx.x;
    int warp = tid >> 5, lane = tid & 31;
    int wm = warp & 1, wn = warp >> 1;
    int n0 = blockIdx.x * 64;
    unsigned a_base = (unsigned)__cvta_generic_to_shared(smA);
    unsigned b_base = (unsigned)__cvta_generic_to_shared(smB);
    int lrow = lane & 15, lk = (lane >> 4) * 8;

    // load full A: tanh(g_comb) fp32 -> bf16 swizzled smem (64x512)
#pragma unroll
    for (int i = 0; i < 32; i++) {
        int ch = i * 128 + tid;
        int r = ch >> 6, c = ch & 63;
        const float* src = g_comb + r * H + c * 8;
        float4 f0 = *(const float4*)(src);
        float4 f1 = *(const float4*)(src + 4);
        uint4 v;
        v.x = pack_bf2(tanhf(f0.x), tanhf(f0.y));
        v.y = pack_bf2(tanhf(f0.z), tanhf(f0.w));
        v.z = pack_bf2(tanhf(f1.x), tanhf(f1.y));
        v.w = pack_bf2(tanhf(f1.z), tanhf(f1.w));
        *(uint4*)(smA + swzA(r, c * 16)) = v;
    }

    float acc[2][4][4] = {};
    float4 f[4][2];
#pragma unroll
    for (int i = 0; i < 4; i++) {
        int ch = i * 128 + tid, r = ch >> 3, c = ch & 7;
        const float* src = W_out + (size_t)(n0 + r) * H + c * 8;
        f[i][0] = *(const float4*)(src);
        f[i][1] = *(const float4*)(src + 4);
    }
    for (int kc = 0; kc < H / 64; kc++) {
        char* buf = smB + (kc & 1) * 8192;
#pragma unroll
        for (int i = 0; i < 4; i++) {
            int ch = i * 128 + tid, r = ch >> 3, c = ch & 7;
            uint4 v;
            v.x = pack_bf2(f[i][0].x, f[i][0].y);
            v.y = pack_bf2(f[i][0].z, f[i][0].w);
            v.z = pack_bf2(f[i][1].x, f[i][1].y);
            v.w = pack_bf2(f[i][1].z, f[i][1].w);
            *(uint4*)(buf + swz(r * 128 + c * 16)) = v;
        }
        __syncthreads();
        if (kc + 1 < H / 64) {
            int k0 = (kc + 1) * 64;
#pragma unroll
            for (int i = 0; i < 4; i++) {
                int ch = i * 128 + tid, r = ch >> 3, c = ch & 7;
                const float* src = W_out + (size_t)(n0 + r) * H + k0 + c * 8;
                f[i][0] = *(const float4*)(src);
                f[i][1] = *(const float4*)(src + 4);
            }
        }
        unsigned bbuf = b_base + (kc & 1) * 8192;
#pragma unroll
        for (int ks = 0; ks < 4; ks++) {
            unsigned af[2][4], bfm[2][4];
#pragma unroll
            for (int mf = 0; mf < 2; mf++) {
                int row = wm * 32 + mf * 16 + lrow;
                LDMX4(af[mf], a_base + swzA(row, (kc * 64 + ks * 16 + lk) * 2));
            }
#pragma unroll
            for (int nh = 0; nh < 2; nh++) {
                int row = wn * 32 + nh * 16 + lrow;
                LDMX4(bfm[nh], bbuf + swz(row * 128 + (ks * 16 + lk) * 2));
            }
#pragma unroll
            for (int mf = 0; mf < 2; mf++)
#pragma unroll
                for (int nf = 0; nf < 4; nf++) {
                    int nh = nf >> 1, nl = nf & 1;
                    MMA16816(acc[mf][nf], af[mf], bfm[nh][nl], bfm[nh][nl + 2]);
                }
        }
    }
    int qr = lane >> 2, qc = lane & 3;
#pragma unroll
    for (int mf = 0; mf < 2; mf++) {
        int m0 = wm * 32 + mf * 16 + qr;
#pragma unroll
        for (int nf = 0; nf < 4; nf++) {
            int n = n0 + wn * 32 + nf * 8 + qc * 2;
            float bo0 = b_out[n], bo1 = b_out[n + 1];
            out[(size_t)m0 * VE + n]           = acc[mf][nf][0] + bo0;
            out[(size_t)m0 * VE + n + 1]       = acc[mf][nf][1] + bo1;
            out[(size_t)(m0 + 8) * VE + n]     = acc[mf][nf][2] + bo0;
            out[(size_t)(m0 + 8) * VE + n + 1] = acc[mf][nf][3] + bo1;
        }
    }
}

// ---------------- tensor-core seqkey (R5/R9 structure, bf16 A) -----------------
__global__ void __launch_bounds__(128) seqkey_mma() {
    __shared__ __align__(128) __nv_bfloat16 As[64 * 64];
    __shared__ __align__(128) __nv_bfloat16 Bs[64 * 64];
    int tid = threadIdx.x;
    int warp = tid >> 5, lane = tid & 31;
    int wm = warp & 1, wn = warp >> 1;
    int n0 = blockIdx.x * 64, s0 = blockIdx.y * 64, b = blockIdx.z;
    const __nv_bfloat16* Ag = g_seqs_bf + ((size_t)b * S_SEQ + s0) * ENC2;
    const __nv_bfloat16* Bg = g_wsk_bf + (size_t)n0 * ENC2;

    float acc[2][4][4] = {};
    unsigned a_base = (unsigned)__cvta_generic_to_shared(As);
    unsigned b_base = (unsigned)__cvta_generic_to_shared(Bs);
    int lrow = lane & 15, lk = (lane >> 4) * 8;

    uint4 pa[4], pb[4];
#pragma unroll
    for (int i = 0; i < 4; i++) {
        int ch = i * 128 + tid, r = ch >> 3, c = ch & 7;
        pa[i] = *(const uint4*)(Ag + (size_t)r * ENC2 + c * 8);
        pb[i] = *(const uint4*)(Bg + (size_t)r * ENC2 + c * 8);
    }
    for (int kc = 0; kc < ENC2 / 64; kc++) {
#pragma unroll
        for (int i = 0; i < 4; i++) {
            int ch = i * 128 + tid, r = ch >> 3, c = ch & 7;
            unsigned off = swz(r * 128 + c * 16);
            *(uint4*)((char*)As + off) = pa[i];
            *(uint4*)((char*)Bs + off) = pb[i];
        }
        __syncthreads();
        if (kc + 1 < ENC2 / 64) {
            int k0 = (kc + 1) * 64;
#pragma unroll
            for (int i = 0; i < 4; i++) {
                int ch = i * 128 + tid, r = ch >> 3, c = ch & 7;
                pa[i] = *(const uint4*)(Ag + (size_t)r * ENC2 + k0 + c * 8);
                pb[i] = *(const uint4*)(Bg + (size_t)r * ENC2 + k0 + c * 8);
            }
        }
#pragma unroll
        for (int ks = 0; ks < 4; ks++) {
            int kb = ks * 16;
            unsigned af[2][4], bfm[2][4];
#pragma unroll
            for (int mf = 0; mf < 2; mf++) {
                int row = wm * 32 + mf * 16 + lrow;
                LDMX4(af[mf], a_base + swz(row * 128 + (kb + lk) * 2));
            }
#pragma unroll
            for (int nh = 0; nh < 2; nh++) {
                int row = wn * 32 + nh * 16 + lrow;
                LDMX4(bfm[nh], b_base + swz(row * 128 + (kb + lk) * 2));
            }
#pragma unroll
            for (int mf = 0; mf < 2; mf++)
#pragma unroll
                for (int nf = 0; nf < 4; nf++) {
                    int nh = nf >> 1, nl = nf & 1;
                    MMA16816(acc[mf][nf], af[mf], bfm[nh][nl], bfm[nh][nl + 2]);
                }
        }
        __syncthreads();
    }
    const float* h1p = g_h1 + b * H + n0 + wn * 32;
    int qr = lane >> 2, qc = lane & 3;
#pragma unroll
    for (int mf = 0; mf < 2; mf++) {
        float s0v = 0.f, s1v = 0.f;
#pragma unroll
        for (int nf = 0; nf < 4; nf++) {
            float h0v = h1p[nf * 8 + qc * 2 + 0];
            float h1v = h1p[nf * 8 + qc * 2 + 1];
            s0v += tanhf(acc[mf][nf][0]) * h0v + tanhf(acc[mf][nf][1]) * h1v;
            s1v += tanhf(acc[mf][nf][2]) * h0v + tanhf(acc[mf][nf][3]) * h1v;
        }
        s0v += __shfl_xor_sync(0xffffffffu, s0v, 1);
        s0v += __shfl_xor_sync(0xffffffffu, s0v, 2);
        s1v += __shfl_xor_sync(0xffffffffu, s1v, 1);
        s1v += __shfl_xor_sync(0xffffffffu, s1v, 2);
        if (qc == 0) {
            int srow = s0 + wm * 32 + mf * 16 + qr;
            atomicAdd(&g_seqE[b * S_SEQ + srow], s0v);
            atomicAdd(&g_seqE[b * S_SEQ + srow + 8], s1v);
        }
    }
}

// ---------------- final: smem scatter-max + register-cached log_softmax --------
#define FINAL_SMEM (VE * 4 + 1024 * 4)
__global__ void __launch_bounds__(1024) final_kernel(float* __restrict__ out,
                                                     const unsigned char* __restrict__ mask,
                                                     const int* __restrict__ ext) {
    extern __shared__ char dynsm[];
    unsigned* copy_s = (unsigned*)dynsm;
    float* sh = (float*)(dynsm + VE * 4);
    int b = blockIdx.x, t = threadIdx.x;
    unsigned negord = ordf(NEGINF);
    for (int j = t; j < VE; j += 1024) copy_s[j] = negord;
    __syncthreads();
    if (t < 512) {
        float e = mask[b * S_SEQ + t] ? 1e-12f : g_seqE[b * S_SEQ + t];
        atomicMax(&copy_s[ext[b * S_SEQ + t]], ordf(e));
    }
    __syncthreads();
    float* row = out + (size_t)b * VE;
    float v[32];
    float mx = -INFINITY;
#pragma unroll
    for (int i = 0; i < 32; i++) {
        int j = t + i * 1024;
        if (j < VE) {
            float lg = row[j];
            float cf = iordf(copy_s[j]);
            if (cf == NEGINF) cf = 0.f;
            float val = lg + cf;
            if (val == 0.f) val = NEGINF;
            v[i] = val;
            mx = fmaxf(mx, val);
        } else {
            v[i] = NEGINF;
        }
    }
    sh[t] = mx;
    __syncthreads();
    for (int s = 512; s; s >>= 1) { if (t < s) sh[t] = fmaxf(sh[t], sh[t + s]); __syncthreads(); }
    float m = sh[0];
    __syncthreads();
    float sum = 0.f;
#pragma unroll
    for (int i = 0; i < 32; i++) sum += expf(v[i] - m);
    sh[t] = sum;
    __syncthreads();
    for (int s = 512; s; s >>= 1) { if (t < s) sh[t] += sh[t + s]; __syncthreads(); }
    float lse = m + logf(sh[0]);
#pragma unroll
    for (int i = 0; i < 32; i++) {
        int j = t + i * 1024;
        if (j < VE) row[j] = v[i] - lse;
    }
}

// ============================ host launcher ==================================
extern "C" void kernel_launch(void* const* d_in, const int* in_sizes, int n_in,
                              void* d_out, int out_size) {
    (void)in_sizes; (void)n_in; (void)out_size;
    const int*           ids      = (const int*)d_in[0];
    const float*         prev_ctx = (const float*)d_in[1];
    const float*         h0       = (const float*)d_in[2];
    const float*         c0       = (const float*)d_in[3];
    const float*         enc      = (const float*)d_in[4];
    const float*         seqs     = (const float*)d_in[5];
    const unsigned char* mask     = (const unsigned char*)d_in[6];
    const int*           ext      = (const int*)d_in[7];
    const float*         embed    = (const float*)d_in[8];
    const float*         W_reduce = (const float*)d_in[9];
    const float*         b_reduce = (const float*)d_in[10];
    const float*         W_key    = (const float*)d_in[11];
    const float*         b_key    = (const float*)d_in[12];
    const float*         W_comb   = (const float*)d_in[13];
    const float*         b_comb   = (const float*)d_in[14];
    const float*         W_seqkey = (const float*)d_in[15];
    const float*         W_ih     = (const float*)d_in[16];
    const float*         W_hh     = (const float*)d_in[17];
    const float*         b_ih     = (const float*)d_in[18];
    const float*         b_hh     = (const float*)d_in[19];
    const float*         W_out    = (const float*)d_in[20];
    const float*         b_out    = (const float*)d_in[21];
    float* out = (float*)d_out;

    void *p_x, *p_gates, *p_cat2, *p_comb;
    cudaGetSymbolAddress(&p_x, g_x);
    cudaGetSymbolAddress(&p_gates, g_gates);
    cudaGetSymbolAddress(&p_cat2, g_cat2);
    cudaGetSymbolAddress(&p_comb, g_comb);

    static int smem_set = 0;
    if (!smem_set) {
        cudaFuncSetAttribute(wout_mma, cudaFuncAttributeMaxDynamicSharedMemorySize, 81920);
        cudaFuncSetAttribute(final_kernel, cudaFuncAttributeMaxDynamicSharedMemorySize, FINAL_SMEM);
        smem_set = 1;
    }

    // 0) init + bf16 conversions
    init_kernel<<<4096, 512>>>(ids, prev_ctx, embed, seqs, W_seqkey, out);
    // 1+2) dual: x = cat @ W_reduce.T + b_reduce  |  gates += h0 @ W_hh.T  (z=16)
    {
        dim3 g((4 * H) / BN, 2, 16);
        gemm_dual<<<g, 256>>>(W_reduce, b_reduce, h0, W_hh);
    }
    // 3) gates += x @ W_ih.T  (z=16)
    {
        dim3 g((4 * H) / BN, 1, 16);
        gemm_sk<<<g, 256>>>((const float*)p_x, EMB, W_ih, EMB,
                            (float*)p_gates, 4 * H, EMB, nullptr);
    }
    // 4) LSTM elementwise + kb (256 blocks)
    {
        dim3 g(B, 4);
        lstm_kernel<<<g, 128>>>(c0, b_ih, b_hh, b_key, out);
    }
    // 5) seq-key GEMM + tanh + dot(h1) (dominant)
    {
        dim3 g(H / 64, S_SEQ / 64, B);
        seqkey_mma<<<g, 128>>>();
    }
    // 6) key projection
    {
        dim3 g(B, 8);
        keyproj_kernel<<<g, 256>>>(W_key);
    }
    // 7) energies (full-chip grid — DRAM streaming)
    energies_kernel<<<(B * S_ENC * 32) / 256, 256>>>(enc);
    // 8) softmax -> attn weights
    attnsoftmax_kernel<<<B, S_ENC>>>(out);
    // 9) context (writes g_cat2 + out ctx region directly)
    {
        dim3 g(B, 8);
        context_kernel<<<g, 512>>>(enc, out);
    }
    // 10) comb_pre = cat(h1,ctx) @ W_comb.T + b_comb  (z=16)
    {
        dim3 g(H / BN, 1, 16);
        gemm_sk<<<g, 256>>>((const float*)p_cat2, 1024, W_comb, 1024,
                            (float*)p_comb, H, 1024, b_comb);
    }
    // 11) logits = tanh(comb) @ W_out.T + b_out (tanh folded into A-load)
    wout_mma<<<V / 64, 128, 81920>>>(W_out, b_out, out);
    // 12) smem scatter-max + log_softmax
    final_kernel<<<B, 1024, FINAL_SMEM>>>(out, mask, ext);
}

// round 16
// speedup vs baseline: 1.2182x; 1.0087x over previous
#include <cuda_runtime.h>
#include <cuda_bf16.h>
#include <math.h>

#define B 64
#define H 512
#define EMB 512
#define V 32000
#define S_ENC 512
#define S_SEQ 512
#define ENC2 512
#define OOV 50
#define VE (V + OOV) /* 32050 */
#define NEGINF (-1e12f)
#define BVE ((size_t)B * VE)

// ---------------- scratch (device globals) -----------------------------------
__device__ float    g_cat[B * 1024];
__device__ float    g_x[B * EMB];
__device__ float    g_gates[B * 4 * H];
__device__ float    g_h1[B * H];
__device__ float    g_keyp[B * H];
__device__ float    g_kb[B];
__device__ float    g_energies[B * S_ENC];
__device__ float    g_cat2[B * 1024];
__device__ float    g_comb[B * H];
__device__ float    g_seqE[B * S_SEQ];
__device__ __nv_bfloat16 g_seqs_bf[(size_t)B * S_SEQ * ENC2]; // 33.5MB
__device__ __nv_bfloat16 g_wsk_bf[H * ENC2];                  // 0.5MB

__device__ __forceinline__ float sigmoidf_(float x) { return 1.f / (1.f + expf(-x)); }
__device__ __forceinline__ unsigned ordf(float f) {
    unsigned u = __float_as_uint(f);
    return (u & 0x80000000u) ? ~u : (u | 0x80000000u);
}
__device__ __forceinline__ float iordf(unsigned u) {
    return (u & 0x80000000u) ? __uint_as_float(u ^ 0x80000000u) : __uint_as_float(~u);
}
__device__ __forceinline__ unsigned pack_bf2(float x, float y) {
    __nv_bfloat162 h = __floats2bfloat162_rn(x, y);
    return *reinterpret_cast<unsigned*>(&h);
}
__device__ __forceinline__ unsigned swz(unsigned byte_off) {
    return byte_off ^ ((byte_off >> 3) & 0x70); // 128B-row swizzle
}
// swizzle for 1024B rows: XOR 16B-unit index with (row&7)
__device__ __forceinline__ unsigned swzA(int row, int byteInRow) {
    return (unsigned)(row * 1024 + ((((byteInRow >> 4) ^ (row & 7)) << 4) | (byteInRow & 15)));
}

#define MMA16816(C, A, B0, B1) asm volatile( \
    "mma.sync.aligned.m16n8k16.row.col.f32.bf16.bf16.f32 " \
    "{%0,%1,%2,%3},{%4,%5,%6,%7},{%8,%9},{%0,%1,%2,%3};" \
    : "+f"(C[0]), "+f"(C[1]), "+f"(C[2]), "+f"(C[3]) \
    : "r"(A[0]), "r"(A[1]), "r"(A[2]), "r"(A[3]), "r"(B0), "r"(B1))

#define LDMX4(R, ADDR) asm volatile( \
    "ldmatrix.sync.aligned.m8n8.x4.shared.b16 {%0,%1,%2,%3},[%4];" \
    : "=r"(R[0]), "=r"(R[1]), "=r"(R[2]), "=r"(R[3]) : "r"(ADDR))

// ---------------- init --------------------------------------------------------
__global__ void init_kernel(const int* __restrict__ ids,
                            const float* __restrict__ prev_ctx,
                            const float* __restrict__ embed,
                            const float* __restrict__ seqs,
                            const float* __restrict__ W_seqkey,
                            float* __restrict__ out) {
    int stride = gridDim.x * blockDim.x;
    int i0 = blockIdx.x * blockDim.x + threadIdx.x;
    for (int j = i0; j < B * OOV; j += stride) {
        int b = j / OOV, k = j % OOV;
        out[b * VE + V + k] = 0.f;
    }
    for (int j = i0; j < B * S_SEQ; j += stride) g_seqE[j] = 0.f;
    for (int j = i0; j < B * EMB; j += stride) g_x[j] = 0.f;
    for (int j = i0; j < B * 4 * H; j += stride) g_gates[j] = 0.f;
    for (int j = i0; j < B * H; j += stride) {
        g_comb[j] = 0.f;
        out[BVE + j] = 0.f; // ctx region of out (context_kernel atomicAdds here)
    }
    for (int j = i0; j < B * 1024; j += stride) {
        int b = j >> 10, k = j & 1023;
        g_cat[j] = (k < EMB) ? embed[(size_t)ids[b] * EMB + k] : prev_ctx[b * H + (k - EMB)];
        if (k >= 512) g_cat2[j] = 0.f;
    }
    // bf16 conversions (vectorized by 4)
    {
        const size_t n4 = (size_t)B * S_SEQ * ENC2 / 4;
        const float4* src = (const float4*)seqs;
        uint2* dst = (uint2*)g_seqs_bf;
        for (size_t j = i0; j < n4; j += stride) {
            float4 f = src[j];
            dst[j] = make_uint2(pack_bf2(f.x, f.y), pack_bf2(f.z, f.w));
        }
    }
    {
        const size_t n4 = (size_t)H * ENC2 / 4;
        const float4* src = (const float4*)W_seqkey;
        uint2* dst = (uint2*)g_wsk_bf;
        for (size_t j = i0; j < n4; j += stride) {
            float4 f = src[j];
            dst[j] = make_uint2(pack_bf2(f.x, f.y), pack_bf2(f.z, f.w));
        }
    }
}

// ---------------- split-K SIMT GEMM (M=64): atomicAdd epilogue ----------------
#define BM 64
#define BN 64
#define BK 16
__device__ __forceinline__ void gemm_body(const float* __restrict__ A, int lda,
                                          const float* __restrict__ Bw, int ldb,
                                          float* __restrict__ C, int ldc,
                                          int K, int nsplit,
                                          const float* __restrict__ bias) {
    __shared__ float As[BK][BM + 1];
    __shared__ float Bs[BK][BN + 1];
    int tid = threadIdx.x;
    int n0 = blockIdx.x * BN;
    int kslice = K / nsplit;
    int kbeg = blockIdx.z * kslice;
    int tm = (tid / 16) * 4;
    int tn = (tid % 16) * 4;
    float acc[4][4] = {};
    int lrow = tid >> 2;
    int lkc = (tid & 3) * 4;

    for (int k0 = kbeg; k0 < kbeg + kslice; k0 += BK) {
        float4 av = *reinterpret_cast<const float4*>(A + (size_t)lrow * lda + k0 + lkc);
        As[lkc + 0][lrow] = av.x; As[lkc + 1][lrow] = av.y;
        As[lkc + 2][lrow] = av.z; As[lkc + 3][lrow] = av.w;
        float4 bv = *reinterpret_cast<const float4*>(Bw + (size_t)(n0 + lrow) * ldb + k0 + lkc);
        Bs[lkc + 0][lrow] = bv.x; Bs[lkc + 1][lrow] = bv.y;
        Bs[lkc + 2][lrow] = bv.z; Bs[lkc + 3][lrow] = bv.w;
        __syncthreads();
#pragma unroll
        for (int kk = 0; kk < BK; ++kk) {
            float a0 = As[kk][tm + 0], a1 = As[kk][tm + 1];
            float a2 = As[kk][tm + 2], a3 = As[kk][tm + 3];
            float b0 = Bs[kk][tn + 0], b1 = Bs[kk][tn + 1];
            float b2 = Bs[kk][tn + 2], b3 = Bs[kk][tn + 3];
            acc[0][0] += a0 * b0; acc[0][1] += a0 * b1; acc[0][2] += a0 * b2; acc[0][3] += a0 * b3;
            acc[1][0] += a1 * b0; acc[1][1] += a1 * b1; acc[1][2] += a1 * b2; acc[1][3] += a1 * b3;
            acc[2][0] += a2 * b0; acc[2][1] += a2 * b1; acc[2][2] += a2 * b2; acc[2][3] += a2 * b3;
            acc[3][0] += a3 * b0; acc[3][1] += a3 * b1; acc[3][2] += a3 * b2; acc[3][3] += a3 * b3;
        }
        __syncthreads();
    }
#pragma unroll
    for (int i = 0; i < 4; i++)
#pragma unroll
        for (int j = 0; j < 4; j++) {
            int cgl = n0 + tn + j;
            float v = acc[i][j];
            if (bias && blockIdx.z == 0) v += bias[cgl];
            atomicAdd(C + (size_t)(tm + i) * ldc + cgl, v);
        }
}

__global__ void gemm_sk(const float* __restrict__ A, int lda,
                        const float* __restrict__ Bw, int ldb,
                        float* __restrict__ C, int ldc,
                        int K, const float* __restrict__ bias) {
    gemm_body(A, lda, Bw, ldb, C, ldc, K, gridDim.z, bias);
}

__global__ void gemm_dual(const float* __restrict__ Wr,
                          const float* __restrict__ br,
                          const float* __restrict__ h0,
                          const float* __restrict__ Whh) {
    if (blockIdx.y == 0) {
        if (blockIdx.x >= EMB / BN) return;
        gemm_body(g_cat, 1024, Wr, 1024, g_x, EMB, 1024, gridDim.z, br);
    } else {
        gemm_body(h0, H, Whh, H, g_gates, 4 * H, H, gridDim.z, nullptr);
    }
}

// ---------------- fused LSTM (recomputed per block) + key projection ----------
// grid (B, 8), 256 threads. Each block recomputes full h1[b,:] into smem (8x
// redundant; gates+c0 are L2-resident), then computes its 64 keyp columns.
// Block nc==0 additionally writes h1/c1/g_h1/g_cat2 and kb.
__global__ void __launch_bounds__(256) lstm_keyproj_kernel(
    const float* __restrict__ c0, const float* __restrict__ b_ih,
    const float* __restrict__ b_hh, const float* __restrict__ b_key,
    const float* __restrict__ W_key, float* __restrict__ out) {
    int b = blockIdx.x, nc = blockIdx.y;
    int t = threadIdx.x;
    __shared__ float hs[H];
    __shared__ float part[4][64];
    const float* gr = g_gates + b * 4 * H;
#pragma unroll
    for (int half = 0; half < 2; half++) {
        int h = t + half * 256;
        float ig = sigmoidf_(gr[h] + b_ih[h] + b_hh[h]);
        float fg = sigmoidf_(gr[H + h] + b_ih[H + h] + b_hh[H + h]);
        float gg = tanhf(gr[2 * H + h] + b_ih[2 * H + h] + b_hh[2 * H + h]);
        float og = sigmoidf_(gr[3 * H + h] + b_ih[3 * H + h] + b_hh[3 * H + h]);
        float c1 = fg * c0[b * H + h] + ig * gg;
        float h1 = og * tanhf(c1);
        hs[h] = h1;
        if (nc == 0) {
            g_h1[b * H + h] = h1;
            g_cat2[b * 1024 + h] = h1;
            out[BVE + B * H + b * H + h] = h1;
            out[BVE + 2 * B * H + b * H + h] = c1;
        }
    }
    __syncthreads();
    if (nc == 0) {
        // kb = b_key . h1 (per-warp shuffle + atomic; g_kb written only here)
        float val = b_key[t] * hs[t] + b_key[t + 256] * hs[t + 256];
        for (int o = 16; o; o >>= 1) val += __shfl_down_sync(0xffffffffu, val, o);
        __shared__ float wsum[8];
        if ((t & 31) == 0) wsum[t >> 5] = val;
        __syncthreads();
        if (t == 0) {
            float s = 0.f;
#pragma unroll
            for (int i = 0; i < 8; i++) s += wsum[i];
            g_kb[b] = s;
        }
    }
    int n = nc * 64 + (t & 63);
    int hp = t >> 6;
    const float* wp = W_key + (size_t)(hp * 128) * H + n;
    const float* hh = hs + hp * 128;
    float acc = 0.f;
#pragma unroll 16
    for (int k = 0; k < 128; k++) acc += hh[k] * wp[(size_t)k * H];
    part[hp][t & 63] = acc;
    __syncthreads();
    if (t < 64)
        g_keyp[b * H + nc * 64 + t] = part[0][t] + part[1][t] + part[2][t] + part[3][t];
}

// ---------------- energies (raw, full-chip grid) -------------------------------
__global__ void energies_kernel(const float* __restrict__ enc) {
    int gw = (blockIdx.x * blockDim.x + threadIdx.x) >> 5;
    int lane = threadIdx.x & 31;
    if (gw >= B * S_ENC) return;
    int b = gw / S_ENC;
    const float* er = enc + (size_t)gw * H;
    const float* kp = g_keyp + b * H;
    float e = 0.f, sm = 0.f;
#pragma unroll 4
    for (int k = lane; k < H; k += 32) {
        float x = er[k];
        e += x * kp[k];
        sm += x;
    }
    for (int o = 16; o; o >>= 1) {
        e += __shfl_down_sync(0xffffffffu, e, o);
        sm += __shfl_down_sync(0xffffffffu, sm, o);
    }
    if (lane == 0) g_energies[gw] = (sm == 0.f) ? 1e-12f : (e + g_kb[b]);
}

// ---------------- fused softmax (recomputed per block) + context ---------------
// grid (B, 8), 512 threads. Each block redoes the 512-wide softmax from raw
// g_energies (small, L2-hot), then accumulates its 64-s context chunk.
// Block chunk==0 writes the attn weights to out.
__global__ void __launch_bounds__(512) softmax_context_kernel(const float* __restrict__ enc,
                                                              float* __restrict__ out) {
    int b = blockIdx.x, chunk = blockIdx.y, t = threadIdx.x;
    __shared__ float w[S_ENC];
    __shared__ float red[S_ENC];
    float e = g_energies[b * S_ENC + t];
    red[t] = e;
    __syncthreads();
    for (int s = 256; s; s >>= 1) { if (t < s) red[t] = fmaxf(red[t], red[t + s]); __syncthreads(); }
    float m = red[0];
    __syncthreads();
    float ex = expf(e - m);
    red[t] = ex;
    __syncthreads();
    for (int s = 256; s; s >>= 1) { if (t < s) red[t] += red[t + s]; __syncthreads(); }
    float wt = ex / red[0];
    w[t] = wt;
    if (chunk == 0) out[BVE + 3 * B * H + b * S_ENC + t] = wt;
    __syncthreads();
    int s0 = chunk * 64;
    const float* er = enc + ((size_t)b * S_ENC + s0) * H + t;
    float acc = 0.f;
#pragma unroll 4
    for (int s = 0; s < 64; s++) acc += w[s0 + s] * er[(size_t)s * H];
    atomicAdd(&g_cat2[b * 1024 + 512 + t], acc);
    atomicAdd(&out[BVE + b * H + t], acc);
}

// ---------------- W_out MMA: A = tanh(g_comb) converted in-kernel --------------
__global__ void __launch_bounds__(128) wout_mma(const float* __restrict__ W_out,
                                                const float* __restrict__ b_out,
                                                float* __restrict__ out) {
    extern __shared__ char dynsm[];
    char* smA = dynsm;              // 65536
    char* smB = dynsm + 65536;      // 2 * 8192
    int tid = threadIdx.x;
    int warp = tid >> 5, lane = tid & 31;
    int wm = warp & 1, wn = warp >> 1;
    int n0 = blockIdx.x * 64;
    unsigned a_base = (unsigned)__cvta_generic_to_shared(smA);
    unsigned b_base = (unsigned)__cvta_generic_to_shared(smB);
    int lrow = lane & 15, lk = (lane >> 4) * 8;

    // load full A: tanh(g_comb) fp32 -> bf16 swizzled smem (64x512)
#pragma unroll
    for (int i = 0; i < 32; i++) {
        int ch = i * 128 + tid;
        int r = ch >> 6, c = ch & 63;
        const float* src = g_comb + r * H + c * 8;
        float4 f0 = *(const float4*)(src);
        float4 f1 = *(const float4*)(src + 4);
        uint4 v;
        v.x = pack_bf2(tanhf(f0.x), tanhf(f0.y));
        v.y = pack_bf2(tanhf(f0.z), tanhf(f0.w));
        v.z = pack_bf2(tanhf(f1.x), tanhf(f1.y));
        v.w = pack_bf2(tanhf(f1.z), tanhf(f1.w));
        *(uint4*)(smA + swzA(r, c * 16)) = v;
    }

    float acc[2][4][4] = {};
    float4 f[4][2];
#pragma unroll
    for (int i = 0; i < 4; i++) {
        int ch = i * 128 + tid, r = ch >> 3, c = ch & 7;
        const float* src = W_out + (size_t)(n0 + r) * H + c * 8;
        f[i][0] = *(const float4*)(src);
        f[i][1] = *(const float4*)(src + 4);
    }
    for (int kc = 0; kc < H / 64; kc++) {
        char* buf = smB + (kc & 1) * 8192;
#pragma unroll
        for (int i = 0; i < 4; i++) {
            int ch = i * 128 + tid, r = ch >> 3, c = ch & 7;
            uint4 v;
            v.x = pack_bf2(f[i][0].x, f[i][0].y);
            v.y = pack_bf2(f[i][0].z, f[i][0].w);
            v.z = pack_bf2(f[i][1].x, f[i][1].y);
            v.w = pack_bf2(f[i][1].z, f[i][1].w);
            *(uint4*)(buf + swz(r * 128 + c * 16)) = v;
        }
        __syncthreads();
        if (kc + 1 < H / 64) {
            int k0 = (kc + 1) * 64;
#pragma unroll
            for (int i = 0; i < 4; i++) {
                int ch = i * 128 + tid, r = ch >> 3, c = ch & 7;
                const float* src = W_out + (size_t)(n0 + r) * H + k0 + c * 8;
                f[i][0] = *(const float4*)(src);
                f[i][1] = *(const float4*)(src + 4);
            }
        }
        unsigned bbuf = b_base + (kc & 1) * 8192;
#pragma unroll
        for (int ks = 0; ks < 4; ks++) {
            unsigned af[2][4], bfm[2][4];
#pragma unroll
            for (int mf = 0; mf < 2; mf++) {
                int row = wm * 32 + mf * 16 + lrow;
                LDMX4(af[mf], a_base + swzA(row, (kc * 64 + ks * 16 + lk) * 2));
            }
#pragma unroll
            for (int nh = 0; nh < 2; nh++) {
                int row = wn * 32 + nh * 16 + lrow;
                LDMX4(bfm[nh], bbuf + swz(row * 128 + (ks * 16 + lk) * 2));
            }
#pragma unroll
            for (int mf = 0; mf < 2; mf++)
#pragma unroll
                for (int nf = 0; nf < 4; nf++) {
                    int nh = nf >> 1, nl = nf & 1;
                    MMA16816(acc[mf][nf], af[mf], bfm[nh][nl], bfm[nh][nl + 2]);
                }
        }
    }
    int qr = lane >> 2, qc = lane & 3;
#pragma unroll
    for (int mf = 0; mf < 2; mf++) {
        int m0 = wm * 32 + mf * 16 + qr;
#pragma unroll
        for (int nf = 0; nf < 4; nf++) {
            int n = n0 + wn * 32 + nf * 8 + qc * 2;
            float bo0 = b_out[n], bo1 = b_out[n + 1];
            out[(size_t)m0 * VE + n]           = acc[mf][nf][0] + bo0;
            out[(size_t)m0 * VE + n + 1]       = acc[mf][nf][1] + bo1;
            out[(size_t)(m0 + 8) * VE + n]     = acc[mf][nf][2] + bo0;
            out[(size_t)(m0 + 8) * VE + n + 1] = acc[mf][nf][3] + bo1;
        }
    }
}

// ---------------- tensor-core seqkey (R5/R9 structure, bf16 A) -----------------
__global__ void __launch_bounds__(128) seqkey_mma() {
    __shared__ __align__(128) __nv_bfloat16 As[64 * 64];
    __shared__ __align__(128) __nv_bfloat16 Bs[64 * 64];
    int tid = threadIdx.x;
    int warp = tid >> 5, lane = tid & 31;
    int wm = warp & 1, wn = warp >> 1;
    int n0 = blockIdx.x * 64, s0 = blockIdx.y * 64, b = blockIdx.z;
    const __nv_bfloat16* Ag = g_seqs_bf + ((size_t)b * S_SEQ + s0) * ENC2;
    const __nv_bfloat16* Bg = g_wsk_bf + (size_t)n0 * ENC2;

    float acc[2][4][4] = {};
    unsigned a_base = (unsigned)__cvta_generic_to_shared(As);
    unsigned b_base = (unsigned)__cvta_generic_to_shared(Bs);
    int lrow = lane & 15, lk = (lane >> 4) * 8;

    uint4 pa[4], pb[4];
#pragma unroll
    for (int i = 0; i < 4; i++) {
        int ch = i * 128 + tid, r = ch >> 3, c = ch & 7;
        pa[i] = *(const uint4*)(Ag + (size_t)r * ENC2 + c * 8);
        pb[i] = *(const uint4*)(Bg + (size_t)r * ENC2 + c * 8);
    }
    for (int kc = 0; kc < ENC2 / 64; kc++) {
#pragma unroll
        for (int i = 0; i < 4; i++) {
            int ch = i * 128 + tid, r = ch >> 3, c = ch & 7;
            unsigned off = swz(r * 128 + c * 16);
            *(uint4*)((char*)As + off) = pa[i];
            *(uint4*)((char*)Bs + off) = pb[i];
        }
        __syncthreads();
        if (kc + 1 < ENC2 / 64) {
            int k0 = (kc + 1) * 64;
#pragma unroll
            for (int i = 0; i < 4; i++) {
                int ch = i * 128 + tid, r = ch >> 3, c = ch & 7;
                pa[i] = *(const uint4*)(Ag + (size_t)r * ENC2 + k0 + c * 8);
                pb[i] = *(const uint4*)(Bg + (size_t)r * ENC2 + k0 + c * 8);
            }
        }
#pragma unroll
        for (int ks = 0; ks < 4; ks++) {
            int kb = ks * 16;
            unsigned af[2][4], bfm[2][4];
#pragma unroll
            for (int mf = 0; mf < 2; mf++) {
                int row = wm * 32 + mf * 16 + lrow;
                LDMX4(af[mf], a_base + swz(row * 128 + (kb + lk) * 2));
            }
#pragma unroll
            for (int nh = 0; nh < 2; nh++) {
                int row = wn * 32 + nh * 16 + lrow;
                LDMX4(bfm[nh], b_base + swz(row * 128 + (kb + lk) * 2));
            }
#pragma unroll
            for (int mf = 0; mf < 2; mf++)
#pragma unroll
                for (int nf = 0; nf < 4; nf++) {
                    int nh = nf >> 1, nl = nf & 1;
                    MMA16816(acc[mf][nf], af[mf], bfm[nh][nl], bfm[nh][nl + 2]);
                }
        }
        __syncthreads();
    }
    const float* h1p = g_h1 + b * H + n0 + wn * 32;
    int qr = lane >> 2, qc = lane & 3;
#pragma unroll
    for (int mf = 0; mf < 2; mf++) {
        float s0v = 0.f, s1v = 0.f;
#pragma unroll
        for (int nf = 0; nf < 4; nf++) {
            float h0v = h1p[nf * 8 + qc * 2 + 0];
            float h1v = h1p[nf * 8 + qc * 2 + 1];
            s0v += tanhf(acc[mf][nf][0]) * h0v + tanhf(acc[mf][nf][1]) * h1v;
            s1v += tanhf(acc[mf][nf][2]) * h0v + tanhf(acc[mf][nf][3]) * h1v;
        }
        s0v += __shfl_xor_sync(0xffffffffu, s0v, 1);
        s0v += __shfl_xor_sync(0xffffffffu, s0v, 2);
        s1v += __shfl_xor_sync(0xffffffffu, s1v, 1);
        s1v += __shfl_xor_sync(0xffffffffu, s1v, 2);
        if (qc == 0) {
            int srow = s0 + wm * 32 + mf * 16 + qr;
            atomicAdd(&g_seqE[b * S_SEQ + srow], s0v);
            atomicAdd(&g_seqE[b * S_SEQ + srow + 8], s1v);
        }
    }
}

// ---------------- final: smem scatter-max + register-cached log_softmax --------
#define FINAL_SMEM (VE * 4 + 1024 * 4)
__global__ void __launch_bounds__(1024) final_kernel(float* __restrict__ out,
                                                     const unsigned char* __restrict__ mask,
                                                     const int* __restrict__ ext) {
    extern __shared__ char dynsm[];
    unsigned* copy_s = (unsigned*)dynsm;
    float* sh = (float*)(dynsm + VE * 4);
    int b = blockIdx.x, t = threadIdx.x;
    unsigned negord = ordf(NEGINF);
    for (int j = t; j < VE; j += 1024) copy_s[j] = negord;
    __syncthreads();
    if (t < 512) {
        float e = mask[b * S_SEQ + t] ? 1e-12f : g_seqE[b * S_SEQ + t];
        atomicMax(&copy_s[ext[b * S_SEQ + t]], ordf(e));
    }
    __syncthreads();
    float* row = out + (size_t)b * VE;
    float v[32];
    float mx = -INFINITY;
#pragma unroll
    for (int i = 0; i < 32; i++) {
        int j = t + i * 1024;
        if (j < VE) {
            float lg = row[j];
            float cf = iordf(copy_s[j]);
            if (cf == NEGINF) cf = 0.f;
            float val = lg + cf;
            if (val == 0.f) val = NEGINF;
            v[i] = val;
            mx = fmaxf(mx, val);
        } else {
            v[i] = NEGINF;
        }
    }
    sh[t] = mx;
    __syncthreads();
    for (int s = 512; s; s >>= 1) { if (t < s) sh[t] = fmaxf(sh[t], sh[t + s]); __syncthreads(); }
    float m = sh[0];
    __syncthreads();
    float sum = 0.f;
#pragma unroll
    for (int i = 0; i < 32; i++) sum += expf(v[i] - m);
    sh[t] = sum;
    __syncthreads();
    for (int s = 512; s; s >>= 1) { if (t < s) sh[t] += sh[t + s]; __syncthreads(); }
    float lse = m + logf(sh[0]);
#pragma unroll
    for (int i = 0; i < 32; i++) {
        int j = t + i * 1024;
        if (j < VE) row[j] = v[i] - lse;
    }
}

// ============================ host launcher ==================================
extern "C" void kernel_launch(void* const* d_in, const int* in_sizes, int n_in,
                              void* d_out, int out_size) {
    (void)in_sizes; (void)n_in; (void)out_size;
    const int*           ids      = (const int*)d_in[0];
    const float*         prev_ctx = (const float*)d_in[1];
    const float*         h0       = (const float*)d_in[2];
    const float*         c0       = (const float*)d_in[3];
    const float*         enc      = (const float*)d_in[4];
    const float*         seqs     = (const float*)d_in[5];
    const unsigned char* mask     = (const unsigned char*)d_in[6];
    const int*           ext      = (const int*)d_in[7];
    const float*         embed    = (const float*)d_in[8];
    const float*         W_reduce = (const float*)d_in[9];
    const float*         b_reduce = (const float*)d_in[10];
    const float*         W_key    = (const float*)d_in[11];
    const float*         b_key    = (const float*)d_in[12];
    const float*         W_comb   = (const float*)d_in[13];
    const float*         b_comb   = (const float*)d_in[14];
    const float*         W_seqkey = (const float*)d_in[15];
    const float*         W_ih     = (const float*)d_in[16];
    const float*         W_hh     = (const float*)d_in[17];
    const float*         b_ih     = (const float*)d_in[18];
    const float*         b_hh     = (const float*)d_in[19];
    const float*         W_out    = (const float*)d_in[20];
    const float*         b_out    = (const float*)d_in[21];
    float* out = (float*)d_out;

    void *p_x, *p_gates, *p_cat2, *p_comb;
    cudaGetSymbolAddress(&p_x, g_x);
    cudaGetSymbolAddress(&p_gates, g_gates);
    cudaGetSymbolAddress(&p_cat2, g_cat2);
    cudaGetSymbolAddress(&p_comb, g_comb);

    static int smem_set = 0;
    if (!smem_set) {
        cudaFuncSetAttribute(wout_mma, cudaFuncAttributeMaxDynamicSharedMemorySize, 81920);
        cudaFuncSetAttribute(final_kernel, cudaFuncAttributeMaxDynamicSharedMemorySize, FINAL_SMEM);
        smem_set = 1;
    }

    // 0) init + bf16 conversions
    init_kernel<<<4096, 512>>>(ids, prev_ctx, embed, seqs, W_seqkey, out);
    // 1+2) dual: x = cat @ W_reduce.T + b_reduce  |  gates += h0 @ W_hh.T  (z=16)
    {
        dim3 g((4 * H) / BN, 2, 16);
        gemm_dual<<<g, 256>>>(W_reduce, b_reduce, h0, W_hh);
    }
    // 3) gates += x @ W_ih.T  (z=16)
    {
        dim3 g((4 * H) / BN, 1, 16);
        gemm_sk<<<g, 256>>>((const float*)p_x, EMB, W_ih, EMB,
                            (float*)p_gates, 4 * H, EMB, nullptr);
    }
    // 4) fused LSTM + key projection (lstm recomputed per block)
    {
        dim3 g(B, 8);
        lstm_keyproj_kernel<<<g, 256>>>(c0, b_ih, b_hh, b_key, W_key, out);
    }
    // 5) seq-key GEMM + tanh + dot(h1) (needs g_h1, written by nc==0 blocks above)
    {
        dim3 g(H / 64, S_SEQ / 64, B);
        seqkey_mma<<<g, 128>>>();
    }
    // 6) energies (raw; full-chip grid — DRAM streaming)
    energies_kernel<<<(B * S_ENC * 32) / 256, 256>>>(enc);
    // 7) fused softmax (recomputed per block) + context
    {
        dim3 g(B, 8);
        softmax_context_kernel<<<g, 512>>>(enc, out);
    }
    // 8) comb_pre = cat(h1,ctx) @ W_comb.T + b_comb  (z=16)
    {
        dim3 g(H / BN, 1, 16);
        gemm_sk<<<g, 256>>>((const float*)p_cat2, 1024, W_comb, 1024,
                            (float*)p_comb, H, 1024, b_comb);
    }
    // 9) logits = tanh(comb) @ W_out.T + b_out (tanh folded into A-load)
    wout_mma<<<V / 64, 128, 81920>>>(W_out, b_out, out);
    // 10) smem scatter-max + log_softmax
    final_kernel<<<B, 1024, FINAL_SMEM>>>(out, mask, ext);
}

// round 17
// speedup vs baseline: 1.3207x; 1.0841x over previous
#include <cuda_runtime.h>
#include <cuda_bf16.h>
#include <math.h>

#define B 64
#define H 512
#define EMB 512
#define V 32000
#define S_ENC 512
#define S_SEQ 512
#define ENC2 512
#define OOV 50
#define VE (V + OOV) /* 32050 */
#define NEGINF (-1e12f)
#define BVE ((size_t)B * VE)

// ---------------- scratch (device globals) -----------------------------------
__device__ float    g_cat[B * 1024];
__device__ float    g_x[B * EMB];
__device__ float    g_gates[B * 4 * H];
__device__ float    g_h1[B * H];
__device__ float    g_keyp[B * H];
__device__ float    g_kb[B];
__device__ float    g_energies[B * S_ENC];
__device__ float    g_cat2[B * 1024];
__device__ float    g_comb[B * H];
__device__ float    g_seqE[B * S_SEQ];
__device__ __nv_bfloat16 g_seqs_bf[(size_t)B * S_SEQ * ENC2]; // 33.5MB
__device__ __nv_bfloat16 g_wsk_bf[H * ENC2];                  // 0.5MB

__device__ __forceinline__ float sigmoidf_(float x) { return 1.f / (1.f + expf(-x)); }
__device__ __forceinline__ unsigned ordf(float f) {
    unsigned u = __float_as_uint(f);
    return (u & 0x80000000u) ? ~u : (u | 0x80000000u);
}
__device__ __forceinline__ float iordf(unsigned u) {
    return (u & 0x80000000u) ? __uint_as_float(u ^ 0x80000000u) : __uint_as_float(~u);
}
__device__ __forceinline__ unsigned pack_bf2(float x, float y) {
    __nv_bfloat162 h = __floats2bfloat162_rn(x, y);
    return *reinterpret_cast<unsigned*>(&h);
}
__device__ __forceinline__ unsigned swz(unsigned byte_off) {
    return byte_off ^ ((byte_off >> 3) & 0x70); // 128B-row swizzle
}
// swizzle for 1024B rows: XOR 16B-unit index with (row&7)
__device__ __forceinline__ unsigned swzA(int row, int byteInRow) {
    return (unsigned)(row * 1024 + ((((byteInRow >> 4) ^ (row & 7)) << 4) | (byteInRow & 15)));
}

#define MMA16816(C, A, B0, B1) asm volatile( \
    "mma.sync.aligned.m16n8k16.row.col.f32.bf16.bf16.f32 " \
    "{%0,%1,%2,%3},{%4,%5,%6,%7},{%8,%9},{%0,%1,%2,%3};" \
    : "+f"(C[0]), "+f"(C[1]), "+f"(C[2]), "+f"(C[3]) \
    : "r"(A[0]), "r"(A[1]), "r"(A[2]), "r"(A[3]), "r"(B0), "r"(B1))

#define LDMX4(R, ADDR) asm volatile( \
    "ldmatrix.sync.aligned.m8n8.x4.shared.b16 {%0,%1,%2,%3},[%4];" \
    : "=r"(R[0]), "=r"(R[1]), "=r"(R[2]), "=r"(R[3]) : "r"(ADDR))

// ---------------- init --------------------------------------------------------
__global__ void init_kernel(const int* __restrict__ ids,
                            const float* __restrict__ prev_ctx,
                            const float* __restrict__ embed,
                            const float* __restrict__ seqs,
                            const float* __restrict__ W_seqkey,
                            float* __restrict__ out) {
    int stride = gridDim.x * blockDim.x;
    int i0 = blockIdx.x * blockDim.x + threadIdx.x;
    for (int j = i0; j < B * OOV; j += stride) {
        int b = j / OOV, k = j % OOV;
        out[b * VE + V + k] = 0.f;
    }
    for (int j = i0; j < B * S_SEQ; j += stride) g_seqE[j] = 0.f;
    for (int j = i0; j < B * EMB; j += stride) g_x[j] = 0.f;
    for (int j = i0; j < B * 4 * H; j += stride) g_gates[j] = 0.f;
    for (int j = i0; j < B * H; j += stride) {
        g_comb[j] = 0.f;
        g_keyp[j] = 0.f;            // keyproj split-K accumulates here
        out[BVE + j] = 0.f;         // ctx region of out
    }
    for (int j = i0; j < B * 1024; j += stride) {
        int b = j >> 10, k = j & 1023;
        g_cat[j] = (k < EMB) ? embed[(size_t)ids[b] * EMB + k] : prev_ctx[b * H + (k - EMB)];
        if (k >= 512) g_cat2[j] = 0.f;
    }
    // bf16 conversions (vectorized by 4)
    {
        const size_t n4 = (size_t)B * S_SEQ * ENC2 / 4;
        const float4* src = (const float4*)seqs;
        uint2* dst = (uint2*)g_seqs_bf;
        for (size_t j = i0; j < n4; j += stride) {
            float4 f = src[j];
            dst[j] = make_uint2(pack_bf2(f.x, f.y), pack_bf2(f.z, f.w));
        }
    }
    {
        const size_t n4 = (size_t)H * ENC2 / 4;
        const float4* src = (const float4*)W_seqkey;
        uint2* dst = (uint2*)g_wsk_bf;
        for (size_t j = i0; j < n4; j += stride) {
            float4 f = src[j];
            dst[j] = make_uint2(pack_bf2(f.x, f.y), pack_bf2(f.z, f.w));
        }
    }
}

// ---------------- split-K SIMT GEMM (M=64): atomicAdd epilogue ----------------
#define BM 64
#define BN 64
#define BK 16
__device__ __forceinline__ void gemm_body(const float* __restrict__ A, int lda,
                                          const float* __restrict__ Bw, int ldb,
                                          float* __restrict__ C, int ldc,
                                          int K, int nsplit,
                                          const float* __restrict__ bias) {
    __shared__ float As[BK][BM + 1];
    __shared__ float Bs[BK][BN + 1];
    int tid = threadIdx.x;
    int n0 = blockIdx.x * BN;
    int kslice = K / nsplit;
    int kbeg = blockIdx.z * kslice;
    int tm = (tid / 16) * 4;
    int tn = (tid % 16) * 4;
    float acc[4][4] = {};
    int lrow = tid >> 2;
    int lkc = (tid & 3) * 4;

    for (int k0 = kbeg; k0 < kbeg + kslice; k0 += BK) {
        float4 av = *reinterpret_cast<const float4*>(A + (size_t)lrow * lda + k0 + lkc);
        As[lkc + 0][lrow] = av.x; As[lkc + 1][lrow] = av.y;
        As[lkc + 2][lrow] = av.z; As[lkc + 3][lrow] = av.w;
        float4 bv = *reinterpret_cast<const float4*>(Bw + (size_t)(n0 + lrow) * ldb + k0 + lkc);
        Bs[lkc + 0][lrow] = bv.x; Bs[lkc + 1][lrow] = bv.y;
        Bs[lkc + 2][lrow] = bv.z; Bs[lkc + 3][lrow] = bv.w;
        __syncthreads();
#pragma unroll
        for (int kk = 0; kk < BK; ++kk) {
            float a0 = As[kk][tm + 0], a1 = As[kk][tm + 1];
            float a2 = As[kk][tm + 2], a3 = As[kk][tm + 3];
            float b0 = Bs[kk][tn + 0], b1 = Bs[kk][tn + 1];
            float b2 = Bs[kk][tn + 2], b3 = Bs[kk][tn + 3];
            acc[0][0] += a0 * b0; acc[0][1] += a0 * b1; acc[0][2] += a0 * b2; acc[0][3] += a0 * b3;
            acc[1][0] += a1 * b0; acc[1][1] += a1 * b1; acc[1][2] += a1 * b2; acc[1][3] += a1 * b3;
            acc[2][0] += a2 * b0; acc[2][1] += a2 * b1; acc[2][2] += a2 * b2; acc[2][3] += a2 * b3;
            acc[3][0] += a3 * b0; acc[3][1] += a3 * b1; acc[3][2] += a3 * b2; acc[3][3] += a3 * b3;
        }
        __syncthreads();
    }
#pragma unroll
    for (int i = 0; i < 4; i++)
#pragma unroll
        for (int j = 0; j < 4; j++) {
            int cgl = n0 + tn + j;
            float v = acc[i][j];
            if (bias && blockIdx.z == 0) v += bias[cgl];
            atomicAdd(C + (size_t)(tm + i) * ldc + cgl, v);
        }
}

__global__ void gemm_sk(const float* __restrict__ A, int lda,
                        const float* __restrict__ Bw, int ldb,
                        float* __restrict__ C, int ldc,
                        int K, const float* __restrict__ bias) {
    gemm_body(A, lda, Bw, ldb, C, ldc, K, gridDim.z, bias);
}

__global__ void gemm_dual(const float* __restrict__ Wr,
                          const float* __restrict__ br,
                          const float* __restrict__ h0,
                          const float* __restrict__ Whh) {
    if (blockIdx.y == 0) {
        if (blockIdx.x >= EMB / BN) return;
        gemm_body(g_cat, 1024, Wr, 1024, g_x, EMB, 1024, gridDim.z, br);
    } else {
        gemm_body(h0, H, Whh, H, g_gates, 4 * H, H, gridDim.z, nullptr);
    }
}

// ---------------- NN split-K GEMM: C[m,n] += sum_k A[m,k]*Bw[k,n] --------------
// Used for keyp = h1 @ W_key (W_key stored [k=H][n=H] row-major).
__global__ void __launch_bounds__(256) gemm_nn_sk(const float* __restrict__ A, int lda,
                                                  const float* __restrict__ Bw, int ldb,
                                                  float* __restrict__ C, int ldc,
                                                  int K) {
    __shared__ float As[BK][BM + 1];
    __shared__ float Bs[BK][BN + 1];
    int tid = threadIdx.x;
    int n0 = blockIdx.x * BN;
    int kslice = K / gridDim.z;
    int kbeg = blockIdx.z * kslice;
    int tm = (tid / 16) * 4;
    int tn = (tid % 16) * 4;
    float acc[4][4] = {};
    int lrow = tid >> 2;         // A: row 0..63
    int lkc = (tid & 3) * 4;     // A: k-chunk
    int bkr = tid >> 4;          // B: k-row 0..15
    int bnc = (tid & 15) * 4;    // B: n-chunk

    for (int k0 = kbeg; k0 < kbeg + kslice; k0 += BK) {
        float4 av = *reinterpret_cast<const float4*>(A + (size_t)lrow * lda + k0 + lkc);
        As[lkc + 0][lrow] = av.x; As[lkc + 1][lrow] = av.y;
        As[lkc + 2][lrow] = av.z; As[lkc + 3][lrow] = av.w;
        float4 bv = *reinterpret_cast<const float4*>(Bw + (size_t)(k0 + bkr) * ldb + n0 + bnc);
        Bs[bkr][bnc + 0] = bv.x; Bs[bkr][bnc + 1] = bv.y;
        Bs[bkr][bnc + 2] = bv.z; Bs[bkr][bnc + 3] = bv.w;
        __syncthreads();
#pragma unroll
        for (int kk = 0; kk < BK; ++kk) {
            float a0 = As[kk][tm + 0], a1 = As[kk][tm + 1];
            float a2 = As[kk][tm + 2], a3 = As[kk][tm + 3];
            float b0 = Bs[kk][tn + 0], b1 = Bs[kk][tn + 1];
            float b2 = Bs[kk][tn + 2], b3 = Bs[kk][tn + 3];
            acc[0][0] += a0 * b0; acc[0][1] += a0 * b1; acc[0][2] += a0 * b2; acc[0][3] += a0 * b3;
            acc[1][0] += a1 * b0; acc[1][1] += a1 * b1; acc[1][2] += a1 * b2; acc[1][3] += a1 * b3;
            acc[2][0] += a2 * b0; acc[2][1] += a2 * b1; acc[2][2] += a2 * b2; acc[2][3] += a2 * b3;
            acc[3][0] += a3 * b0; acc[3][1] += a3 * b1; acc[3][2] += a3 * b2; acc[3][3] += a3 * b3;
        }
        __syncthreads();
    }
#pragma unroll
    for (int i = 0; i < 4; i++)
#pragma unroll
        for (int j = 0; j < 4; j++)
            atomicAdd(C + (size_t)(tm + i) * ldc + n0 + tn + j, acc[i][j]);
}

// ---------------- LSTM elementwise + kb (1 block per b) ------------------------
__global__ void __launch_bounds__(512) lstm_kernel(
    const float* __restrict__ c0, const float* __restrict__ b_ih,
    const float* __restrict__ b_hh, const float* __restrict__ b_key,
    float* __restrict__ out) {
    int b = blockIdx.x, h = threadIdx.x;
    const float* gr = g_gates + b * 4 * H;
    float ig = sigmoidf_(gr[h] + b_ih[h] + b_hh[h]);
    float fg = sigmoidf_(gr[H + h] + b_ih[H + h] + b_hh[H + h]);
    float gg = tanhf(gr[2 * H + h] + b_ih[2 * H + h] + b_hh[2 * H + h]);
    float og = sigmoidf_(gr[3 * H + h] + b_ih[3 * H + h] + b_hh[3 * H + h]);
    float c1 = fg * c0[b * H + h] + ig * gg;
    float h1 = og * tanhf(c1);
    g_h1[b * H + h] = h1;
    g_cat2[b * 1024 + h] = h1;
    out[BVE + B * H + b * H + h] = h1;
    out[BVE + 2 * B * H + b * H + h] = c1;
    float val = b_key[h] * h1;
    for (int o = 16; o; o >>= 1) val += __shfl_down_sync(0xffffffffu, val, o);
    __shared__ float wsum[16];
    if ((h & 31) == 0) wsum[h >> 5] = val;
    __syncthreads();
    if (h == 0) {
        float s = 0.f;
#pragma unroll
        for (int i = 0; i < 16; i++) s += wsum[i];
        g_kb[b] = s;
    }
}

// ---------------- energies (raw, full-chip grid) -------------------------------
__global__ void energies_kernel(const float* __restrict__ enc) {
    int gw = (blockIdx.x * blockDim.x + threadIdx.x) >> 5;
    int lane = threadIdx.x & 31;
    if (gw >= B * S_ENC) return;
    int b = gw / S_ENC;
    const float* er = enc + (size_t)gw * H;
    const float* kp = g_keyp + b * H;
    float e = 0.f, sm = 0.f;
#pragma unroll 4
    for (int k = lane; k < H; k += 32) {
        float x = er[k];
        e += x * kp[k];
        sm += x;
    }
    for (int o = 16; o; o >>= 1) {
        e += __shfl_down_sync(0xffffffffu, e, o);
        sm += __shfl_down_sync(0xffffffffu, sm, o);
    }
    if (lane == 0) g_energies[gw] = (sm == 0.f) ? 1e-12f : (e + g_kb[b]);
}

// ---------------- fused softmax (recomputed per block) + context ---------------
__global__ void __launch_bounds__(512) softmax_context_kernel(const float* __restrict__ enc,
                                                              float* __restrict__ out) {
    int b = blockIdx.x, chunk = blockIdx.y, t = threadIdx.x;
    __shared__ float w[S_ENC];
    __shared__ float red[S_ENC];
    float e = g_energies[b * S_ENC + t];
    red[t] = e;
    __syncthreads();
    for (int s = 256; s; s >>= 1) { if (t < s) red[t] = fmaxf(red[t], red[t + s]); __syncthreads(); }
    float m = red[0];
    __syncthreads();
    float ex = expf(e - m);
    red[t] = ex;
    __syncthreads();
    for (int s = 256; s; s >>= 1) { if (t < s) red[t] += red[t + s]; __syncthreads(); }
    float wt = ex / red[0];
    w[t] = wt;
    if (chunk == 0) out[BVE + 3 * B * H + b * S_ENC + t] = wt;
    __syncthreads();
    int s0 = chunk * 64;
    const float* er = enc + ((size_t)b * S_ENC + s0) * H + t;
    float acc = 0.f;
#pragma unroll 4
    for (int s = 0; s < 64; s++) acc += w[s0 + s] * er[(size_t)s * H];
    atomicAdd(&g_cat2[b * 1024 + 512 + t], acc);
    atomicAdd(&out[BVE + b * H + t], acc);
}

// ---------------- W_out MMA: A = tanh(g_comb) converted in-kernel --------------
__global__ void __launch_bounds__(128) wout_mma(const float* __restrict__ W_out,
                                                const float* __restrict__ b_out,
                                                float* __restrict__ out) {
    extern __shared__ char dynsm[];
    char* smA = dynsm;              // 65536
    char* smB = dynsm + 65536;      // 2 * 8192
    int tid = threadIdx.x;
    int warp = tid >> 5, lane = tid & 31;
    int wm = warp & 1, wn = warp >> 1;
    int n0 = blockIdx.x * 64;
    unsigned a_base = (unsigned)__cvta_generic_to_shared(smA);
    unsigned b_base = (unsigned)__cvta_generic_to_shared(smB);
    int lrow = lane & 15, lk = (lane >> 4) * 8;

    // load full A: tanh(g_comb) fp32 -> bf16 swizzled smem (64x512)
#pragma unroll
    for (int i = 0; i < 32; i++) {
        int ch = i * 128 + tid;
        int r = ch >> 6, c = ch & 63;
        const float* src = g_comb + r * H + c * 8;
        float4 f0 = *(const float4*)(src);
        float4 f1 = *(const float4*)(src + 4);
        uint4 v;
        v.x = pack_bf2(tanhf(f0.x), tanhf(f0.y));
        v.y = pack_bf2(tanhf(f0.z), tanhf(f0.w));
        v.z = pack_bf2(tanhf(f1.x), tanhf(f1.y));
        v.w = pack_bf2(tanhf(f1.z), tanhf(f1.w));
        *(uint4*)(smA + swzA(r, c * 16)) = v;
    }

    float acc[2][4][4] = {};
    float4 f[4][2];
#pragma unroll
    for (int i = 0; i < 4; i++) {
        int ch = i * 128 + tid, r = ch >> 3, c = ch & 7;
        const float* src = W_out + (size_t)(n0 + r) * H + c * 8;
        f[i][0] = *(const float4*)(src);
        f[i][1] = *(const float4*)(src + 4);
    }
    for (int kc = 0; kc < H / 64; kc++) {
        char* buf = smB + (kc & 1) * 8192;
#pragma unroll
        for (int i = 0; i < 4; i++) {
            int ch = i * 128 + tid, r = ch >> 3, c = ch & 7;
            uint4 v;
            v.x = pack_bf2(f[i][0].x, f[i][0].y);
            v.y = pack_bf2(f[i][0].z, f[i][0].w);
            v.z = pack_bf2(f[i][1].x, f[i][1].y);
            v.w = pack_bf2(f[i][1].z, f[i][1].w);
            *(uint4*)(buf + swz(r * 128 + c * 16)) = v;
        }
        __syncthreads();
        if (kc + 1 < H / 64) {
            int k0 = (kc + 1) * 64;
#pragma unroll
            for (int i = 0; i < 4; i++) {
                int ch = i * 128 + tid, r = ch >> 3, c = ch & 7;
                const float* src = W_out + (size_t)(n0 + r) * H + k0 + c * 8;
                f[i][0] = *(const float4*)(src);
                f[i][1] = *(const float4*)(src + 4);
            }
        }
        unsigned bbuf = b_base + (kc & 1) * 8192;
#pragma unroll
        for (int ks = 0; ks < 4; ks++) {
            unsigned af[2][4], bfm[2][4];
#pragma unroll
            for (int mf = 0; mf < 2; mf++) {
                int row = wm * 32 + mf * 16 + lrow;
                LDMX4(af[mf], a_base + swzA(row, (kc * 64 + ks * 16 + lk) * 2));
            }
#pragma unroll
            for (int nh = 0; nh < 2; nh++) {
                int row = wn * 32 + nh * 16 + lrow;
                LDMX4(bfm[nh], bbuf + swz(row * 128 + (ks * 16 + lk) * 2));
            }
#pragma unroll
            for (int mf = 0; mf < 2; mf++)
#pragma unroll
                for (int nf = 0; nf < 4; nf++) {
                    int nh = nf >> 1, nl = nf & 1;
                    MMA16816(acc[mf][nf], af[mf], bfm[nh][nl], bfm[nh][nl + 2]);
                }
        }
    }
    int qr = lane >> 2, qc = lane & 3;
#pragma unroll
    for (int mf = 0; mf < 2; mf++) {
        int m0 = wm * 32 + mf * 16 + qr;
#pragma unroll
        for (int nf = 0; nf < 4; nf++) {
            int n = n0 + wn * 32 + nf * 8 + qc * 2;
            float bo0 = b_out[n], bo1 = b_out[n + 1];
            out[(size_t)m0 * VE + n]           = acc[mf][nf][0] + bo0;
            out[(size_t)m0 * VE + n + 1]       = acc[mf][nf][1] + bo1;
            out[(size_t)(m0 + 8) * VE + n]     = acc[mf][nf][2] + bo0;
            out[(size_t)(m0 + 8) * VE + n + 1] = acc[mf][nf][3] + bo1;
        }
    }
}

// ---------------- tensor-core seqkey (R5/R9 structure, bf16 A) -----------------
__global__ void __launch_bounds__(128) seqkey_mma() {
    __shared__ __align__(128) __nv_bfloat16 As[64 * 64];
    __shared__ __align__(128) __nv_bfloat16 Bs[64 * 64];
    int tid = threadIdx.x;
    int warp = tid >> 5, lane = tid & 31;
    int wm = warp & 1, wn = warp >> 1;
    int n0 = blockIdx.x * 64, s0 = blockIdx.y * 64, b = blockIdx.z;
    const __nv_bfloat16* Ag = g_seqs_bf + ((size_t)b * S_SEQ + s0) * ENC2;
    const __nv_bfloat16* Bg = g_wsk_bf + (size_t)n0 * ENC2;

    float acc[2][4][4] = {};
    unsigned a_base = (unsigned)__cvta_generic_to_shared(As);
    unsigned b_base = (unsigned)__cvta_generic_to_shared(Bs);
    int lrow = lane & 15, lk = (lane >> 4) * 8;

    uint4 pa[4], pb[4];
#pragma unroll
    for (int i = 0; i < 4; i++) {
        int ch = i * 128 + tid, r = ch >> 3, c = ch & 7;
        pa[i] = *(const uint4*)(Ag + (size_t)r * ENC2 + c * 8);
        pb[i] = *(const uint4*)(Bg + (size_t)r * ENC2 + c * 8);
    }
    for (int kc = 0; kc < ENC2 / 64; kc++) {
#pragma unroll
        for (int i = 0; i < 4; i++) {
            int ch = i * 128 + tid, r = ch >> 3, c = ch & 7;
            unsigned off = swz(r * 128 + c * 16);
            *(uint4*)((char*)As + off) = pa[i];
            *(uint4*)((char*)Bs + off) = pb[i];
        }
        __syncthreads();
        if (kc + 1 < ENC2 / 64) {
            int k0 = (kc + 1) * 64;
#pragma unroll
            for (int i = 0; i < 4; i++) {
                int ch = i * 128 + tid, r = ch >> 3, c = ch & 7;
                pa[i] = *(const uint4*)(Ag + (size_t)r * ENC2 + k0 + c * 8);
                pb[i] = *(const uint4*)(Bg + (size_t)r * ENC2 + k0 + c * 8);
            }
        }
#pragma unroll
        for (int ks = 0; ks < 4; ks++) {
            int kb = ks * 16;
            unsigned af[2][4], bfm[2][4];
#pragma unroll
            for (int mf = 0; mf < 2; mf++) {
                int row = wm * 32 + mf * 16 + lrow;
                LDMX4(af[mf], a_base + swz(row * 128 + (kb + lk) * 2));
            }
#pragma unroll
            for (int nh = 0; nh < 2; nh++) {
                int row = wn * 32 + nh * 16 + lrow;
                LDMX4(bfm[nh], b_base + swz(row * 128 + (kb + lk) * 2));
            }
#pragma unroll
            for (int mf = 0; mf < 2; mf++)
#pragma unroll
                for (int nf = 0; nf < 4; nf++) {
                    int nh = nf >> 1, nl = nf & 1;
                    MMA16816(acc[mf][nf], af[mf], bfm[nh][nl], bfm[nh][nl + 2]);
                }
        }
        __syncthreads();
    }
    const float* h1p = g_h1 + b * H + n0 + wn * 32;
    int qr = lane >> 2, qc = lane & 3;
#pragma unroll
    for (int mf = 0; mf < 2; mf++) {
        float s0v = 0.f, s1v = 0.f;
#pragma unroll
        for (int nf = 0; nf < 4; nf++) {
            float h0v = h1p[nf * 8 + qc * 2 + 0];
            float h1v = h1p[nf * 8 + qc * 2 + 1];
            s0v += tanhf(acc[mf][nf][0]) * h0v + tanhf(acc[mf][nf][1]) * h1v;
            s1v += tanhf(acc[mf][nf][2]) * h0v + tanhf(acc[mf][nf][3]) * h1v;
        }
        s0v += __shfl_xor_sync(0xffffffffu, s0v, 1);
        s0v += __shfl_xor_sync(0xffffffffu, s0v, 2);
        s1v += __shfl_xor_sync(0xffffffffu, s1v, 1);
        s1v += __shfl_xor_sync(0xffffffffu, s1v, 2);
        if (qc == 0) {
            int srow = s0 + wm * 32 + mf * 16 + qr;
            atomicAdd(&g_seqE[b * S_SEQ + srow], s0v);
            atomicAdd(&g_seqE[b * S_SEQ + srow + 8], s1v);
        }
    }
}

// ---------------- final: smem scatter-max + register-cached log_softmax --------
#define FINAL_SMEM (VE * 4 + 1024 * 4)
__global__ void __launch_bounds__(1024) final_kernel(float* __restrict__ out,
                                                     const unsigned char* __restrict__ mask,
                                                     const int* __restrict__ ext) {
    extern __shared__ char dynsm[];
    unsigned* copy_s = (unsigned*)dynsm;
    float* sh = (float*)(dynsm + VE * 4);
    int b = blockIdx.x, t = threadIdx.x;
    unsigned negord = ordf(NEGINF);
    for (int j = t; j < VE; j += 1024) copy_s[j] = negord;
    __syncthreads();
    if (t < 512) {
        float e = mask[b * S_SEQ + t] ? 1e-12f : g_seqE[b * S_SEQ + t];
        atomicMax(&copy_s[ext[b * S_SEQ + t]], ordf(e));
    }
    __syncthreads();
    float* row = out + (size_t)b * VE;
    float v[32];
    float mx = -INFINITY;
#pragma unroll
    for (int i = 0; i < 32; i++) {
        int j = t + i * 1024;
        if (j < VE) {
            float lg = row[j];
            float cf = iordf(copy_s[j]);
            if (cf == NEGINF) cf = 0.f;
            float val = lg + cf;
            if (val == 0.f) val = NEGINF;
            v[i] = val;
            mx = fmaxf(mx, val);
        } else {
            v[i] = NEGINF;
        }
    }
    sh[t] = mx;
    __syncthreads();
    for (int s = 512; s; s >>= 1) { if (t < s) sh[t] = fmaxf(sh[t], sh[t + s]); __syncthreads(); }
    float m = sh[0];
    __syncthreads();
    float sum = 0.f;
#pragma unroll
    for (int i = 0; i < 32; i++) sum += expf(v[i] - m);
    sh[t] = sum;
    __syncthreads();
    for (int s = 512; s; s >>= 1) { if (t < s) sh[t] += sh[t + s]; __syncthreads(); }
    float lse = m + logf(sh[0]);
#pragma unroll
    for (int i = 0; i < 32; i++) {
        int j = t + i * 1024;
        if (j < VE) row[j] = v[i] - lse;
    }
}

// ============================ host launcher ==================================
extern "C" void kernel_launch(void* const* d_in, const int* in_sizes, int n_in,
                              void* d_out, int out_size) {
    (void)in_sizes; (void)n_in; (void)out_size;
    const int*           ids      = (const int*)d_in[0];
    const float*         prev_ctx = (const float*)d_in[1];
    const float*         h0       = (const float*)d_in[2];
    const float*         c0       = (const float*)d_in[3];
    const float*         enc      = (const float*)d_in[4];
    const float*         seqs     = (const float*)d_in[5];
    const unsigned char* mask     = (const unsigned char*)d_in[6];
    const int*           ext      = (const int*)d_in[7];
    const float*         embed    = (const float*)d_in[8];
    const float*         W_reduce = (const float*)d_in[9];
    const float*         b_reduce = (const float*)d_in[10];
    const float*         W_key    = (const float*)d_in[11];
    const float*         b_key    = (const float*)d_in[12];
    const float*         W_comb   = (const float*)d_in[13];
    const float*         b_comb   = (const float*)d_in[14];
    const float*         W_seqkey = (const float*)d_in[15];
    const float*         W_ih     = (const float*)d_in[16];
    const float*         W_hh     = (const float*)d_in[17];
    const float*         b_ih     = (const float*)d_in[18];
    const float*         b_hh     = (const float*)d_in[19];
    const float*         W_out    = (const float*)d_in[20];
    const float*         b_out    = (const float*)d_in[21];
    float* out = (float*)d_out;

    void *p_x, *p_gates, *p_h1, *p_keyp, *p_cat2, *p_comb;
    cudaGetSymbolAddress(&p_x, g_x);
    cudaGetSymbolAddress(&p_gates, g_gates);
    cudaGetSymbolAddress(&p_h1, g_h1);
    cudaGetSymbolAddress(&p_keyp, g_keyp);
    cudaGetSymbolAddress(&p_cat2, g_cat2);
    cudaGetSymbolAddress(&p_comb, g_comb);

    static int smem_set = 0;
    if (!smem_set) {
        cudaFuncSetAttribute(wout_mma, cudaFuncAttributeMaxDynamicSharedMemorySize, 81920);
        cudaFuncSetAttribute(final_kernel, cudaFuncAttributeMaxDynamicSharedMemorySize, FINAL_SMEM);
        smem_set = 1;
    }

    // 0) init + bf16 conversions
    init_kernel<<<4096, 512>>>(ids, prev_ctx, embed, seqs, W_seqkey, out);
    // 1+2) dual: x = cat @ W_reduce.T + b_reduce  |  gates += h0 @ W_hh.T  (z=16)
    {
        dim3 g((4 * H) / BN, 2, 16);
        gemm_dual<<<g, 256>>>(W_reduce, b_reduce, h0, W_hh);
    }
    // 3) gates += x @ W_ih.T  (z=16)
    {
        dim3 g((4 * H) / BN, 1, 16);
        gemm_sk<<<g, 256>>>((const float*)p_x, EMB, W_ih, EMB,
                            (float*)p_gates, 4 * H, EMB, nullptr);
    }
    // 4) LSTM elementwise + kb
    lstm_kernel<<<B, 512>>>(c0, b_ih, b_hh, b_key, out);
    // 5) seq-key GEMM + tanh + dot(h1) (dominant)
    {
        dim3 g(H / 64, S_SEQ / 64, B);
        seqkey_mma<<<g, 128>>>();
    }
    // 6) key projection as NN split-K GEMM: keyp = h1 @ W_key  (z=16)
    {
        dim3 g(H / BN, 1, 16);
        gemm_nn_sk<<<g, 256>>>((const float*)p_h1, H, W_key, H,
                               (float*)p_keyp, H, H);
    }
    // 7) energies (full-chip grid — DRAM streaming)
    energies_kernel<<<(B * S_ENC * 32) / 256, 256>>>(enc);
    // 8) fused softmax + context
    {
        dim3 g(B, 8);
        softmax_context_kernel<<<g, 512>>>(enc, out);
    }
    // 9) comb_pre = cat(h1,ctx) @ W_comb.T + b_comb  (z=16)
    {
        dim3 g(H / BN, 1, 16);
        gemm_sk<<<g, 256>>>((const float*)p_cat2, 1024, W_comb, 1024,
                            (float*)p_comb, H, 1024, b_comb);
    }
    // 10) logits = tanh(comb) @ W_out.T + b_out (tanh folded into A-load)
    wout_mma<<<V / 64, 128, 81920>>>(W_out, b_out, out);
    // 11) smem scatter-max + log_softmax
    final_kernel<<<B, 1024, FINAL_SMEM>>>(out, mask, ext);
}